// round 1
// baseline (speedup 1.0000x reference)
#include <cuda_runtime.h>
#include <math.h>

#define Gc   2
#define Nn   20000
#define Ee   160000
#define Ff   128
#define Cc   64
#define Hh   8
#define HC   512
#define E2   (Ee + Nn)      // 180000 edges incl self loops, per graph
#define GN   (Gc * Nn)      // 40000
#define GE2  (Gc * E2)      // 360000

#define MINF_ENC 0x007FFFFFu   // fenc(-inf)

// ---------------- scratch (device globals; no cudaMalloc allowed) ----------
__device__ float    g_xl1 [GN * HC];
__device__ float    g_xr1 [GN * HC];
__device__ float    g_acc1[GN * HC];     // layer1 agg -> elu -> h1 (in place)
__device__ float    g_xl2 [GN * Cc];
__device__ float    g_xr2 [GN * Cc];
__device__ float    g_acc2[GN * Cc];     // layer2 agg -> elu -> h2 (in place)
__device__ float    g_logit1[(size_t)GE2 * Hh];
__device__ float    g_logit2[GE2];
__device__ unsigned g_m1  [GN * Hh];
__device__ float    g_den1[GN * Hh];
__device__ unsigned g_m2  [GN];
__device__ float    g_den2[GN];
__device__ float    g_cnt [GN];
__device__ float    g_loop[GN];
__device__ unsigned g_GvEnc[Cc];
__device__ float    g_gpart[Cc];

// ---------------- helpers ----------------
__device__ __forceinline__ unsigned fenc(float f) {
    unsigned u = __float_as_uint(f);
    return (u & 0x80000000u) ? ~u : (u | 0x80000000u);
}
__device__ __forceinline__ float fdec(unsigned u) {
    return __uint_as_float((u & 0x80000000u) ? (u & 0x7fffffffu) : ~u);
}
__device__ __forceinline__ float wsum(float v) {
    v += __shfl_xor_sync(0xffffffffu, v, 16);
    v += __shfl_xor_sync(0xffffffffu, v, 8);
    v += __shfl_xor_sync(0xffffffffu, v, 4);
    v += __shfl_xor_sync(0xffffffffu, v, 2);
    v += __shfl_xor_sync(0xffffffffu, v, 1);
    return v;
}

// ---------------- init ----------------
__global__ void k_init() {
    int i = blockIdx.x * blockDim.x + threadIdx.x;
    if (i < GN * HC) g_acc1[i] = 0.f;
    if (i < GN * Cc) g_acc2[i] = 0.f;
    if (i < GN * Hh) { g_den1[i] = 0.f; g_m1[i] = MINF_ENC; }
    if (i < GN)      { g_den2[i] = 0.f; g_m2[i] = MINF_ENC; g_cnt[i] = 0.f; g_loop[i] = 0.f; }
    if (i < Cc)      g_GvEnc[i] = MINF_ENC;
}

// ---------------- degree + self-loop edge attr ----------------
__global__ void k_deg(const int* __restrict__ ei, const float* __restrict__ ew) {
    int i = blockIdx.x * blockDim.x + threadIdx.x;
    if (i >= Gc * Ee) return;
    int g = i / Ee, e = i - g * Ee;
    int dst = ei[(size_t)g * 2 * Ee + Ee + e];
    atomicAdd(&g_cnt[g * Nn + dst], 1.f);
    atomicAdd(&g_loop[g * Nn + dst], ew[i]);
}
__global__ void k_loopdiv() {
    int i = blockIdx.x * blockDim.x + threadIdx.x;
    if (i < GN) g_loop[i] /= fmaxf(g_cnt[i], 1.f);
}

// ---------------- SGEMM: C = A(MxK) @ W(KxN) + bias ----------------
// BM=128, BN=128, BK=16, 256 threads, 8x8 per thread
__global__ void sgemm_bias(const float* __restrict__ A, const float* __restrict__ W,
                           const float* __restrict__ bias, float* __restrict__ C,
                           int M, int N, int K) {
    __shared__ float As[16][132];
    __shared__ float Bs[16][128];
    int tid = threadIdx.x;
    int tx = tid & 15, ty = tid >> 4;
    int bm = blockIdx.y * 128, bn = blockIdx.x * 128;
    float acc[8][8];
#pragma unroll
    for (int i = 0; i < 8; i++)
#pragma unroll
        for (int j = 0; j < 8; j++) acc[i][j] = 0.f;

    for (int k0 = 0; k0 < K; k0 += 16) {
#pragma unroll
        for (int i = 0; i < 8; i++) {
            int lin = tid + i * 256;
            int r = lin >> 4, c = lin & 15;
            float v = 0.f;
            if (bm + r < M) v = A[(size_t)(bm + r) * K + k0 + c];
            As[c][r] = v;
        }
#pragma unroll
        for (int i = 0; i < 8; i++) {
            int lin = tid + i * 256;
            int r = lin >> 7, c = lin & 127;
            float v = 0.f;
            if (bn + c < N) v = W[(size_t)(k0 + r) * N + bn + c];
            Bs[r][c] = v;
        }
        __syncthreads();
#pragma unroll
        for (int k = 0; k < 16; k++) {
            float a[8], b[8];
#pragma unroll
            for (int i = 0; i < 8; i++) a[i] = As[k][ty * 8 + i];
#pragma unroll
            for (int j = 0; j < 8; j++) b[j] = Bs[k][tx * 8 + j];
#pragma unroll
            for (int i = 0; i < 8; i++)
#pragma unroll
                for (int j = 0; j < 8; j++) acc[i][j] = fmaf(a[i], b[j], acc[i][j]);
        }
        __syncthreads();
    }
#pragma unroll
    for (int i = 0; i < 8; i++) {
        int r = bm + ty * 8 + i;
        if (r >= M) continue;
#pragma unroll
        for (int j = 0; j < 8; j++) {
            int c = bn + tx * 8 + j;
            if (c < N) C[(size_t)r * N + c] = acc[i][j] + bias[c];
        }
    }
}

// ---------------- layer-1 edge logits + segment max ----------------
__global__ void k_edge1_logit(const int* __restrict__ ei, const float* __restrict__ ew,
                              const float* __restrict__ We1, const float* __restrict__ att1) {
    __shared__ float sWe[512], sAtt[512];
    for (int i = threadIdx.x; i < 512; i += blockDim.x) { sWe[i] = We1[i]; sAtt[i] = att1[i]; }
    __syncthreads();
    int wid = (blockIdx.x * blockDim.x + threadIdx.x) >> 5;
    int lane = threadIdx.x & 31;
    if (wid >= GE2) return;
    int g = wid / E2, e = wid - g * E2;
    int src, dst; float w;
    if (e < Ee) {
        src = ei[(size_t)g * 2 * Ee + e];
        dst = ei[(size_t)g * 2 * Ee + Ee + e];
        w = ew[g * Ee + e];
    } else {
        src = dst = e - Ee;
        w = g_loop[g * Nn + src];
    }
    const float* xl = g_xl1 + (size_t)(g * Nn + src) * HC;
    const float* xr = g_xr1 + (size_t)(g * Nn + dst) * HC;
    float* lg = g_logit1 + (size_t)wid * Hh;
    unsigned* mrow = g_m1 + (size_t)(g * Nn + dst) * Hh;
#pragma unroll
    for (int h = 0; h < Hh; h++) {
        float p = 0.f;
#pragma unroll
        for (int j = 0; j < 2; j++) {
            int idx = h * 64 + j * 32 + lane;
            float v = xl[idx] + xr[idx] + w * sWe[idx];
            v = v > 0.f ? v : 0.2f * v;
            p = fmaf(v, sAtt[idx], p);
        }
        p = wsum(p);
        if (lane == 0) {
            lg[h] = p;
            atomicMax(&mrow[h], fenc(p));
        }
    }
}

// ---------------- layer-1 denominators ----------------
__global__ void k_den1(const int* __restrict__ ei) {
    int i = blockIdx.x * blockDim.x + threadIdx.x;
    if (i >= GE2 * Hh) return;
    int g = i / (E2 * Hh);
    int r = i - g * (E2 * Hh);
    int e = r >> 3, h = r & 7;
    int dst = (e < Ee) ? ei[(size_t)g * 2 * Ee + Ee + e] : (e - Ee);
    int ni = (g * Nn + dst) * Hh + h;
    float m = fdec(g_m1[ni]);
    atomicAdd(&g_den1[ni], __expf(g_logit1[i] - m));
}

// ---------------- layer-1 weighted aggregation ----------------
__global__ void k_agg1(const int* __restrict__ ei) {
    int wid = (blockIdx.x * blockDim.x + threadIdx.x) >> 5;
    int lane = threadIdx.x & 31;
    if (wid >= GE2) return;
    int g = wid / E2, e = wid - g * E2;
    int src, dst;
    if (e < Ee) {
        src = ei[(size_t)g * 2 * Ee + e];
        dst = ei[(size_t)g * 2 * Ee + Ee + e];
    } else {
        src = dst = e - Ee;
    }
    float alpha = 0.f;
    if (lane < 8) {
        int ni = (g * Nn + dst) * Hh + lane;
        alpha = __expf(g_logit1[(size_t)wid * Hh + lane] - fdec(g_m1[ni])) / g_den1[ni];
    }
    const float* xl = g_xl1 + (size_t)(g * Nn + src) * HC;
    float* ac = g_acc1 + (size_t)(g * Nn + dst) * HC;
#pragma unroll
    for (int i = 0; i < 16; i++) {
        int idx = i * 32 + lane;
        float a = __shfl_sync(0xffffffffu, alpha, idx >> 6);
        atomicAdd(&ac[idx], a * xl[idx]);
    }
}

// ---------------- elu + bias (in place) ----------------
__global__ void k_elu1(const float* __restrict__ bias1) {
    int i = blockIdx.x * blockDim.x + threadIdx.x;
    if (i >= GN * HC) return;
    float v = g_acc1[i] + bias1[i & 511];
    g_acc1[i] = v > 0.f ? v : (__expf(v) - 1.f);
}
__global__ void k_elu2(const float* __restrict__ bias2) {
    int i = blockIdx.x * blockDim.x + threadIdx.x;
    if (i >= GN * Cc) return;
    float v = g_acc2[i] + bias2[i & 63];
    g_acc2[i] = v > 0.f ? v : (__expf(v) - 1.f);
}

// ---------------- layer-2 edge logits + max ----------------
__global__ void k_edge2_logit(const int* __restrict__ ei, const float* __restrict__ ew,
                              const float* __restrict__ We2, const float* __restrict__ att2) {
    __shared__ float sWe[64], sAtt[64];
    if (threadIdx.x < 64) sWe[threadIdx.x] = We2[threadIdx.x];
    else if (threadIdx.x < 128) sAtt[threadIdx.x - 64] = att2[threadIdx.x - 64];
    __syncthreads();
    int wid = (blockIdx.x * blockDim.x + threadIdx.x) >> 5;
    int lane = threadIdx.x & 31;
    if (wid >= GE2) return;
    int g = wid / E2, e = wid - g * E2;
    int src, dst; float w;
    if (e < Ee) {
        src = ei[(size_t)g * 2 * Ee + e];
        dst = ei[(size_t)g * 2 * Ee + Ee + e];
        w = ew[g * Ee + e];
    } else {
        src = dst = e - Ee;
        w = g_loop[g * Nn + src];
    }
    const float* xl = g_xl2 + (size_t)(g * Nn + src) * Cc;
    const float* xr = g_xr2 + (size_t)(g * Nn + dst) * Cc;
    float p = 0.f;
#pragma unroll
    for (int j = 0; j < 2; j++) {
        int idx = j * 32 + lane;
        float v = xl[idx] + xr[idx] + w * sWe[idx];
        v = v > 0.f ? v : 0.2f * v;
        p = fmaf(v, sAtt[idx], p);
    }
    p = wsum(p);
    if (lane == 0) {
        g_logit2[wid] = p;
        atomicMax(&g_m2[g * Nn + dst], fenc(p));
    }
}

__global__ void k_den2(const int* __restrict__ ei) {
    int i = blockIdx.x * blockDim.x + threadIdx.x;
    if (i >= GE2) return;
    int g = i / E2, e = i - g * E2;
    int dst = (e < Ee) ? ei[(size_t)g * 2 * Ee + Ee + e] : (e - Ee);
    int ni = g * Nn + dst;
    atomicAdd(&g_den2[ni], __expf(g_logit2[i] - fdec(g_m2[ni])));
}

__global__ void k_agg2(const int* __restrict__ ei) {
    int wid = (blockIdx.x * blockDim.x + threadIdx.x) >> 5;
    int lane = threadIdx.x & 31;
    if (wid >= GE2) return;
    int g = wid / E2, e = wid - g * E2;
    int src, dst;
    if (e < Ee) {
        src = ei[(size_t)g * 2 * Ee + e];
        dst = ei[(size_t)g * 2 * Ee + Ee + e];
    } else {
        src = dst = e - Ee;
    }
    int ni = g * Nn + dst;
    float alpha = __expf(g_logit2[wid] - fdec(g_m2[ni])) / g_den2[ni];
    const float* xl = g_xl2 + (size_t)(g * Nn + src) * Cc;
    float* ac = g_acc2 + (size_t)ni * Cc;
#pragma unroll
    for (int j = 0; j < 2; j++) {
        int idx = j * 32 + lane;
        atomicAdd(&ac[idx], alpha * xl[idx]);
    }
}

// ---------------- global max over all nodes/graphs ----------------
__global__ void k_gmax() {
    int col = threadIdx.x & 63;
    int rg = threadIdx.x >> 6;   // 0..3
    float m = -1e30f;
    for (int row = blockIdx.x * 4 + rg; row < GN; row += gridDim.x * 4)
        m = fmaxf(m, g_acc2[(size_t)row * Cc + col]);
    __shared__ float sm[256];
    sm[threadIdx.x] = m;
    __syncthreads();
    if (threadIdx.x < 64) {
        float v = fmaxf(fmaxf(sm[threadIdx.x], sm[threadIdx.x + 64]),
                        fmaxf(sm[threadIdx.x + 128], sm[threadIdx.x + 192]));
        atomicMax(&g_GvEnc[threadIdx.x], fenc(v));
    }
}

// ---------------- Gv -> relu(Gv@Wg+bg) -> gpart = bn + Gv2@Wn[64:,:] ------
__global__ void k_graphvec(const float* __restrict__ Wg, const float* __restrict__ bg,
                           const float* __restrict__ Wn, const float* __restrict__ bn) {
    __shared__ float sGv[64], sGv2[64];
    int t = threadIdx.x;
    sGv[t] = fdec(g_GvEnc[t]);
    __syncthreads();
    float a = bg[t];
#pragma unroll
    for (int c = 0; c < 64; c++) a = fmaf(sGv[c], Wg[c * 64 + t], a);
    sGv2[t] = fmaxf(a, 0.f);
    __syncthreads();
    float b = bn[t];
#pragma unroll
    for (int c = 0; c < 64; c++) b = fmaf(sGv2[c], Wn[(64 + c) * 64 + t], b);
    g_gpart[t] = b;
}

// ---------------- final node MLP ----------------
__global__ void k_final(const float* __restrict__ Wn, const float* __restrict__ Wo,
                        const float* __restrict__ bo, float* __restrict__ out) {
    __shared__ float sWn[64 * 64];
    __shared__ float sWo[64], sGp[64];
    for (int i = threadIdx.x; i < 64 * 64; i += blockDim.x) sWn[i] = Wn[i];
    if (threadIdx.x < 64) { sWo[threadIdx.x] = Wo[threadIdx.x]; sGp[threadIdx.x] = g_gpart[threadIdx.x]; }
    __syncthreads();
    int lane = threadIdx.x & 31;
    int warp = (blockIdx.x * blockDim.x + threadIdx.x) >> 5;
    int nwarps = (gridDim.x * blockDim.x) >> 5;
    float b0 = bo[0];
    for (int node = warp; node < GN; node += nwarps) {
        const float* row = g_acc2 + (size_t)node * Cc;
        float r0 = row[lane], r1 = row[lane + 32];
        float a0 = 0.f, a1 = 0.f;
#pragma unroll
        for (int c = 0; c < 64; c++) {
            float rc = __shfl_sync(0xffffffffu, c < 32 ? r0 : r1, c & 31);
            a0 = fmaf(rc, sWn[c * 64 + lane], a0);
            a1 = fmaf(rc, sWn[c * 64 + lane + 32], a1);
        }
        float t0 = fmaxf(a0 + sGp[lane], 0.f);
        float t1 = fmaxf(a1 + sGp[lane + 32], 0.f);
        float o = wsum(t0 * sWo[lane] + t1 * sWo[lane + 32]);
        if (lane == 0) out[node] = o + b0;
    }
}

// ---------------- launch ----------------
extern "C" void kernel_launch(void* const* d_in, const int* in_sizes, int n_in,
                              void* d_out, int out_size) {
    const float* x     = (const float*)d_in[0];
    const int*   ei    = (const int*)  d_in[1];
    const float* ew    = (const float*)d_in[2];
    const float* Wl1   = (const float*)d_in[3];
    const float* bl1   = (const float*)d_in[4];
    const float* Wr1   = (const float*)d_in[5];
    const float* br1   = (const float*)d_in[6];
    const float* We1   = (const float*)d_in[7];
    const float* att1  = (const float*)d_in[8];
    const float* bias1 = (const float*)d_in[9];
    const float* Wl2   = (const float*)d_in[10];
    const float* bl2   = (const float*)d_in[11];
    const float* Wr2   = (const float*)d_in[12];
    const float* br2   = (const float*)d_in[13];
    const float* We2   = (const float*)d_in[14];
    const float* att2  = (const float*)d_in[15];
    const float* bias2 = (const float*)d_in[16];
    const float* Wg    = (const float*)d_in[17];
    const float* bg    = (const float*)d_in[18];
    const float* Wn    = (const float*)d_in[19];
    const float* bn    = (const float*)d_in[20];
    const float* Wo    = (const float*)d_in[21];
    const float* bo    = (const float*)d_in[22];
    float* out = (float*)d_out;

    float *p_xl1, *p_xr1, *p_h1, *p_xl2, *p_xr2;
    cudaGetSymbolAddress((void**)&p_xl1, g_xl1);
    cudaGetSymbolAddress((void**)&p_xr1, g_xr1);
    cudaGetSymbolAddress((void**)&p_h1,  g_acc1);
    cudaGetSymbolAddress((void**)&p_xl2, g_xl2);
    cudaGetSymbolAddress((void**)&p_xr2, g_xr2);

    const int T = 256;
    k_init<<<(GN * HC + T - 1) / T, T>>>();
    k_deg<<<(Gc * Ee + T - 1) / T, T>>>(ei, ew);
    k_loopdiv<<<(GN + T - 1) / T, T>>>();

    dim3 g1(HC / 128, (GN + 127) / 128);
    sgemm_bias<<<g1, T>>>(x, Wl1, bl1, p_xl1, GN, HC, Ff);
    sgemm_bias<<<g1, T>>>(x, Wr1, br1, p_xr1, GN, HC, Ff);

    int eb = (GE2 * 32 + T - 1) / T;   // warp per edge
    k_edge1_logit<<<eb, T>>>(ei, ew, We1, att1);
    k_den1<<<(GE2 * Hh + T - 1) / T, T>>>(ei);
    k_agg1<<<eb, T>>>(ei);
    k_elu1<<<(GN * HC + T - 1) / T, T>>>(bias1);

    dim3 g2(1, (GN + 127) / 128);
    sgemm_bias<<<g2, T>>>(p_h1, Wl2, bl2, p_xl2, GN, Cc, HC);
    sgemm_bias<<<g2, T>>>(p_h1, Wr2, br2, p_xr2, GN, Cc, HC);

    k_edge2_logit<<<eb, T>>>(ei, ew, We2, att2);
    k_den2<<<(GE2 + T - 1) / T, T>>>(ei);
    k_agg2<<<eb, T>>>(ei);
    k_elu2<<<(GN * Cc + T - 1) / T, T>>>(bias2);

    k_gmax<<<148, 256>>>();
    k_graphvec<<<1, 64>>>(Wg, bg, Wn, bn);
    k_final<<<1184, 256>>>(Wn, Wo, bo, out);
}

// round 2
// speedup vs baseline: 1.4325x; 1.4325x over previous
#include <cuda_runtime.h>
#include <math.h>

#define Gc   2
#define Nn   20000
#define Ee   160000
#define Ff   128
#define Cc   64
#define Hh   8
#define HC   512
#define GN   (Gc * Nn)      // 40000
#define GE   (Gc * Ee)      // 320000

#define MINF_ENC 0x007FFFFFu   // fenc(-inf)

// ---------------- scratch (device globals; no cudaMalloc allowed) ----------
__device__ float    g_xl1 [GN * HC];
__device__ float    g_xr1 [GN * HC];
__device__ float    g_h1  [GN * HC];
__device__ float    g_xl2 [GN * Cc];
__device__ float    g_xr2 [GN * Cc];
__device__ float    g_h2  [GN * Cc];
__device__ int      g_ideg[GN];
__device__ int      g_off [GN + 1];
__device__ int      g_cur [GN];
__device__ int      g_csrc[GE];     // src as global row id (g*Nn+src)
__device__ float    g_cw  [GE];
__device__ float    g_loopsum[GN];
__device__ unsigned g_GvEnc[Cc];
__device__ float    g_gpart[Cc];

// ---------------- helpers ----------------
__device__ __forceinline__ unsigned fenc(float f) {
    unsigned u = __float_as_uint(f);
    return (u & 0x80000000u) ? ~u : (u | 0x80000000u);
}
__device__ __forceinline__ float fdec(unsigned u) {
    return __uint_as_float((u & 0x80000000u) ? (u & 0x7fffffffu) : ~u);
}
__device__ __forceinline__ float wsum(float v) {
    v += __shfl_xor_sync(0xffffffffu, v, 16);
    v += __shfl_xor_sync(0xffffffffu, v, 8);
    v += __shfl_xor_sync(0xffffffffu, v, 4);
    v += __shfl_xor_sync(0xffffffffu, v, 2);
    v += __shfl_xor_sync(0xffffffffu, v, 1);
    return v;
}

// ---------------- init (tiny now) ----------------
__global__ void k_init() {
    int i = blockIdx.x * blockDim.x + threadIdx.x;
    if (i < GN) { g_ideg[i] = 0; g_loopsum[i] = 0.f; }
    if (i < Cc) g_GvEnc[i] = MINF_ENC;
}

// ---------------- degree histogram + loop-weight sum ----------------
__global__ void k_count(const int* __restrict__ ei, const float* __restrict__ ew) {
    int i = blockIdx.x * blockDim.x + threadIdx.x;
    if (i >= GE) return;
    int g = i / Ee, e = i - g * Ee;
    int dst = ei[(size_t)g * 2 * Ee + Ee + e];
    atomicAdd(&g_ideg[g * Nn + dst], 1);
    atomicAdd(&g_loopsum[g * Nn + dst], ew[i]);
}

// ---------------- single-block exclusive scan over GN ----------------
__global__ void k_scan() {
    __shared__ int ssum[1024];
    int t = threadIdx.x;
    const int per = (GN + 1023) / 1024;   // 40
    int s = 0;
    for (int i = 0; i < per; i++) {
        int idx = t * per + i;
        if (idx < GN) s += g_ideg[idx];
    }
    ssum[t] = s;
    __syncthreads();
    for (int d = 1; d < 1024; d <<= 1) {
        int v = (t >= d) ? ssum[t - d] : 0;
        __syncthreads();
        ssum[t] += v;
        __syncthreads();
    }
    int run = ssum[t] - s;   // exclusive prefix of this thread's segment
    for (int i = 0; i < per; i++) {
        int idx = t * per + i;
        if (idx < GN) {
            g_off[idx] = run;
            g_cur[idx] = run;
            run += g_ideg[idx];
        }
    }
    if (t == 0) g_off[GN] = GE;
}

// ---------------- scatter edges into CSR by dst ----------------
__global__ void k_scatter(const int* __restrict__ ei, const float* __restrict__ ew) {
    int i = blockIdx.x * blockDim.x + threadIdx.x;
    if (i >= GE) return;
    int g = i / Ee, e = i - g * Ee;
    int src = ei[(size_t)g * 2 * Ee + e];
    int dst = ei[(size_t)g * 2 * Ee + Ee + e];
    int pos = atomicAdd(&g_cur[g * Nn + dst], 1);
    g_csrc[pos] = g * Nn + src;
    g_cw[pos] = ew[i];
}

// ---------------- dual-output SGEMM: Cl = A@Wl+bl, Cr = A@Wr+br ----------
// logical column space 2N wide; BM=128, BN=128, BK=16, 256 threads, 8x8/thread
__global__ void sgemm_dual(const float* __restrict__ A,
                           const float* __restrict__ Wl, const float* __restrict__ Wr,
                           const float* __restrict__ bl, const float* __restrict__ br,
                           float* __restrict__ Cl, float* __restrict__ Cr,
                           int M, int N, int K) {
    __shared__ float As[16][132];
    __shared__ float Bs[16][128];
    int tid = threadIdx.x;
    int tx = tid & 15, ty = tid >> 4;
    int bm = blockIdx.y * 128, bn = blockIdx.x * 128;
    float acc[8][8];
#pragma unroll
    for (int i = 0; i < 8; i++)
#pragma unroll
        for (int j = 0; j < 8; j++) acc[i][j] = 0.f;

    for (int k0 = 0; k0 < K; k0 += 16) {
#pragma unroll
        for (int i = 0; i < 8; i++) {
            int lin = tid + i * 256;
            int r = lin >> 4, c = lin & 15;
            float v = 0.f;
            if (bm + r < M) v = A[(size_t)(bm + r) * K + k0 + c];
            As[c][r] = v;
        }
#pragma unroll
        for (int i = 0; i < 8; i++) {
            int lin = tid + i * 256;
            int r = lin >> 7, c = lin & 127;
            int cg = bn + c;
            float v;
            if (cg < N) v = Wl[(size_t)(k0 + r) * N + cg];
            else        v = Wr[(size_t)(k0 + r) * N + cg - N];
            Bs[r][c] = v;
        }
        __syncthreads();
#pragma unroll
        for (int k = 0; k < 16; k++) {
            float a[8], b[8];
#pragma unroll
            for (int i = 0; i < 8; i++) a[i] = As[k][ty * 8 + i];
#pragma unroll
            for (int j = 0; j < 8; j++) b[j] = Bs[k][tx * 8 + j];
#pragma unroll
            for (int i = 0; i < 8; i++)
#pragma unroll
                for (int j = 0; j < 8; j++) acc[i][j] = fmaf(a[i], b[j], acc[i][j]);
        }
        __syncthreads();
    }
#pragma unroll
    for (int i = 0; i < 8; i++) {
        int r = bm + ty * 8 + i;
        if (r >= M) continue;
#pragma unroll
        for (int j = 0; j < 8; j++) {
            int cg = bn + tx * 8 + j;
            if (cg < N) Cl[(size_t)r * N + cg]     = acc[i][j] + bl[cg];
            else        Cr[(size_t)r * N + cg - N] = acc[i][j] + br[cg - N];
        }
    }
}

// ---------------- fused layer-1 attention: logits+softmax+agg+bias+elu ----
// one warp per dst node; lane owns 16 contiguous columns (head = lane>>2)
__global__ void k_attn1(const float* __restrict__ We1, const float* __restrict__ att1,
                        const float* __restrict__ bias1) {
    int warp = (blockIdx.x * blockDim.x + threadIdx.x) >> 5;
    int lane = threadIdx.x & 31;
    if (warp >= GN) return;
    int node = warp;
    int base = lane * 16;

    float we[16], at[16], xr[16], acc[16];
    {
        const float4* wep = (const float4*)(We1 + base);
        const float4* atp = (const float4*)(att1 + base);
        const float4* xrp = (const float4*)(g_xr1 + (size_t)node * HC + base);
#pragma unroll
        for (int q = 0; q < 4; q++) {
            float4 a = wep[q]; we[q*4] = a.x; we[q*4+1] = a.y; we[q*4+2] = a.z; we[q*4+3] = a.w;
            float4 b = atp[q]; at[q*4] = b.x; at[q*4+1] = b.y; at[q*4+2] = b.z; at[q*4+3] = b.w;
            float4 c = xrp[q]; xr[q*4] = c.x; xr[q*4+1] = c.y; xr[q*4+2] = c.z; xr[q*4+3] = c.w;
        }
    }
#pragma unroll
    for (int j = 0; j < 16; j++) acc[j] = 0.f;
    float m = -1e30f, den = 0.f;

    int beg = g_off[node], end = g_off[node + 1];
    float wself = g_loopsum[node] / fmaxf((float)(end - beg), 1.f);

    for (int e = beg - 1; e < end; e++) {
        int src; float w;
        if (e < beg) { src = node; w = wself; }
        else         { src = g_csrc[e]; w = g_cw[e]; }
        float xl[16];
        {
            const float4* xlp = (const float4*)(g_xl1 + (size_t)src * HC + base);
#pragma unroll
            for (int q = 0; q < 4; q++) {
                float4 v = xlp[q];
                xl[q*4] = v.x; xl[q*4+1] = v.y; xl[q*4+2] = v.z; xl[q*4+3] = v.w;
            }
        }
        float p = 0.f;
#pragma unroll
        for (int j = 0; j < 16; j++) {
            float v = xl[j] + xr[j] + w * we[j];
            v = v > 0.f ? v : 0.2f * v;
            p = fmaf(v, at[j], p);
        }
        // reduce within 4-lane head group -> per-lane logit for head lane>>2
        p += __shfl_xor_sync(0xffffffffu, p, 1);
        p += __shfl_xor_sync(0xffffffffu, p, 2);
        // online softmax (per-lane scalar state, identical within head group)
        if (p > m) {
            float sc = __expf(m - p);
            den = den * sc + 1.f;
#pragma unroll
            for (int j = 0; j < 16; j++) acc[j] = fmaf(acc[j], sc, xl[j]);
            m = p;
        } else {
            float c = __expf(p - m);
            den += c;
#pragma unroll
            for (int j = 0; j < 16; j++) acc[j] = fmaf(xl[j], c, acc[j]);
        }
    }
    float inv = 1.f / den;
    float* o = g_h1 + (size_t)node * HC + base;
    const float* bi = bias1 + base;
#pragma unroll
    for (int j = 0; j < 16; j++) {
        float v = acc[j] * inv + bi[j];
        o[j] = v > 0.f ? v : (__expf(v) - 1.f);
    }
}

// ---------------- fused layer-2 attention (1 head, C=64) ----------------
__global__ void k_attn2(const float* __restrict__ We2, const float* __restrict__ att2,
                        const float* __restrict__ bias2) {
    int warp = (blockIdx.x * blockDim.x + threadIdx.x) >> 5;
    int lane = threadIdx.x & 31;
    if (warp >= GN) return;
    int node = warp;
    int b2 = lane * 2;

    float2 we = *(const float2*)(We2 + b2);
    float2 at = *(const float2*)(att2 + b2);
    float2 xr = *(const float2*)(g_xr2 + (size_t)node * Cc + b2);
    float acc0 = 0.f, acc1 = 0.f, m = -1e30f, den = 0.f;

    int beg = g_off[node], end = g_off[node + 1];
    float wself = g_loopsum[node] / fmaxf((float)(end - beg), 1.f);

    for (int e = beg - 1; e < end; e++) {
        int src; float w;
        if (e < beg) { src = node; w = wself; }
        else         { src = g_csrc[e]; w = g_cw[e]; }
        float2 xl = *(const float2*)(g_xl2 + (size_t)src * Cc + b2);
        float v0 = xl.x + xr.x + w * we.x;
        float v1 = xl.y + xr.y + w * we.y;
        v0 = v0 > 0.f ? v0 : 0.2f * v0;
        v1 = v1 > 0.f ? v1 : 0.2f * v1;
        float p = wsum(fmaf(v0, at.x, v1 * at.y));
        if (p > m) {
            float sc = __expf(m - p);
            den = den * sc + 1.f;
            acc0 = fmaf(acc0, sc, xl.x);
            acc1 = fmaf(acc1, sc, xl.y);
            m = p;
        } else {
            float c = __expf(p - m);
            den += c;
            acc0 = fmaf(xl.x, c, acc0);
            acc1 = fmaf(xl.y, c, acc1);
        }
    }
    float inv = 1.f / den;
    float v0 = acc0 * inv + bias2[b2];
    float v1 = acc1 * inv + bias2[b2 + 1];
    v0 = v0 > 0.f ? v0 : (__expf(v0) - 1.f);
    v1 = v1 > 0.f ? v1 : (__expf(v1) - 1.f);
    float* o = g_h2 + (size_t)node * Cc + b2;
    o[0] = v0; o[1] = v1;
}

// ---------------- global max over all nodes/graphs ----------------
__global__ void k_gmax() {
    int col = threadIdx.x & 63;
    int rg = threadIdx.x >> 6;   // 0..3
    float m = -1e30f;
    for (int row = blockIdx.x * 4 + rg; row < GN; row += gridDim.x * 4)
        m = fmaxf(m, g_h2[(size_t)row * Cc + col]);
    __shared__ float sm[256];
    sm[threadIdx.x] = m;
    __syncthreads();
    if (threadIdx.x < 64) {
        float v = fmaxf(fmaxf(sm[threadIdx.x], sm[threadIdx.x + 64]),
                        fmaxf(sm[threadIdx.x + 128], sm[threadIdx.x + 192]));
        atomicMax(&g_GvEnc[threadIdx.x], fenc(v));
    }
}

// ---------------- Gv -> relu(Gv@Wg+bg) -> gpart = bn + Gv2@Wn[64:,:] ------
__global__ void k_graphvec(const float* __restrict__ Wg, const float* __restrict__ bg,
                           const float* __restrict__ Wn, const float* __restrict__ bn) {
    __shared__ float sGv[64], sGv2[64];
    int t = threadIdx.x;
    sGv[t] = fdec(g_GvEnc[t]);
    __syncthreads();
    float a = bg[t];
#pragma unroll
    for (int c = 0; c < 64; c++) a = fmaf(sGv[c], Wg[c * 64 + t], a);
    sGv2[t] = fmaxf(a, 0.f);
    __syncthreads();
    float b = bn[t];
#pragma unroll
    for (int c = 0; c < 64; c++) b = fmaf(sGv2[c], Wn[(64 + c) * 64 + t], b);
    g_gpart[t] = b;
}

// ---------------- final node MLP ----------------
__global__ void k_final(const float* __restrict__ Wn, const float* __restrict__ Wo,
                        const float* __restrict__ bo, float* __restrict__ out) {
    __shared__ float sWn[64 * 64];
    __shared__ float sWo[64], sGp[64];
    for (int i = threadIdx.x; i < 64 * 64; i += blockDim.x) sWn[i] = Wn[i];
    if (threadIdx.x < 64) { sWo[threadIdx.x] = Wo[threadIdx.x]; sGp[threadIdx.x] = g_gpart[threadIdx.x]; }
    __syncthreads();
    int lane = threadIdx.x & 31;
    int warp = (blockIdx.x * blockDim.x + threadIdx.x) >> 5;
    int nwarps = (gridDim.x * blockDim.x) >> 5;
    float b0 = bo[0];
    for (int node = warp; node < GN; node += nwarps) {
        const float* row = g_h2 + (size_t)node * Cc;
        float r0 = row[lane], r1 = row[lane + 32];
        float a0 = 0.f, a1 = 0.f;
#pragma unroll
        for (int c = 0; c < 64; c++) {
            float rc = __shfl_sync(0xffffffffu, c < 32 ? r0 : r1, c & 31);
            a0 = fmaf(rc, sWn[c * 64 + lane], a0);
            a1 = fmaf(rc, sWn[c * 64 + lane + 32], a1);
        }
        float t0 = fmaxf(a0 + sGp[lane], 0.f);
        float t1 = fmaxf(a1 + sGp[lane + 32], 0.f);
        float o = wsum(t0 * sWo[lane] + t1 * sWo[lane + 32]);
        if (lane == 0) out[node] = o + b0;
    }
}

// ---------------- launch ----------------
extern "C" void kernel_launch(void* const* d_in, const int* in_sizes, int n_in,
                              void* d_out, int out_size) {
    const float* x     = (const float*)d_in[0];
    const int*   ei    = (const int*)  d_in[1];
    const float* ew    = (const float*)d_in[2];
    const float* Wl1   = (const float*)d_in[3];
    const float* bl1   = (const float*)d_in[4];
    const float* Wr1   = (const float*)d_in[5];
    const float* br1   = (const float*)d_in[6];
    const float* We1   = (const float*)d_in[7];
    const float* att1  = (const float*)d_in[8];
    const float* bias1 = (const float*)d_in[9];
    const float* Wl2   = (const float*)d_in[10];
    const float* bl2   = (const float*)d_in[11];
    const float* Wr2   = (const float*)d_in[12];
    const float* br2   = (const float*)d_in[13];
    const float* We2   = (const float*)d_in[14];
    const float* att2  = (const float*)d_in[15];
    const float* bias2 = (const float*)d_in[16];
    const float* Wg    = (const float*)d_in[17];
    const float* bg    = (const float*)d_in[18];
    const float* Wn    = (const float*)d_in[19];
    const float* bn    = (const float*)d_in[20];
    const float* Wo    = (const float*)d_in[21];
    const float* bo    = (const float*)d_in[22];
    float* out = (float*)d_out;

    float *p_xl1, *p_xr1, *p_h1, *p_xl2, *p_xr2;
    cudaGetSymbolAddress((void**)&p_xl1, g_xl1);
    cudaGetSymbolAddress((void**)&p_xr1, g_xr1);
    cudaGetSymbolAddress((void**)&p_h1,  g_h1);
    cudaGetSymbolAddress((void**)&p_xl2, g_xl2);
    cudaGetSymbolAddress((void**)&p_xr2, g_xr2);

    const int T = 256;
    k_init<<<(GN + T - 1) / T, T>>>();
    k_count<<<(GE + T - 1) / T, T>>>(ei, ew);
    k_scan<<<1, 1024>>>();
    k_scatter<<<(GE + T - 1) / T, T>>>(ei, ew);

    // layer-1 GEMMs: column space 2*512 = 1024 -> grid.x = 8
    sgemm_dual<<<dim3(8, (GN + 127) / 128), T>>>(x, Wl1, Wr1, bl1, br1,
                                                 p_xl1, p_xr1, GN, HC, Ff);
    k_attn1<<<(GN + 7) / 8, T>>>(We1, att1, bias1);

    // layer-2 GEMMs: column space 2*64 = 128 -> grid.x = 1 (full tile)
    sgemm_dual<<<dim3(1, (GN + 127) / 128), T>>>(p_h1, Wl2, Wr2, bl2, br2,
                                                 p_xl2, p_xr2, GN, Cc, HC);
    k_attn2<<<(GN + 7) / 8, T>>>(We2, att2, bias2);

    k_gmax<<<148, 256>>>();
    k_graphvec<<<1, 64>>>(Wg, bg, Wn, bn);
    k_final<<<1184, 256>>>(Wn, Wo, bo, out);
}

// round 3
// speedup vs baseline: 1.9870x; 1.3871x over previous
#include <cuda_runtime.h>
#include <math.h>

#define Gc   2
#define Nn   20000
#define Ee   160000
#define Ff   128
#define Cc   64
#define Hh   8
#define HC   512
#define GN   (Gc * Nn)      // 40000
#define GE   (Gc * Ee)      // 320000

#define MINF_ENC 0x007FFFFFu   // fenc(-inf)

// ---------------- scratch (device globals; no cudaMalloc allowed) ----------
__device__ float    g_xl1 [GN * HC];
__device__ float    g_xr1 [GN * HC];
__device__ float    g_h1  [GN * HC];
__device__ float    g_xl2 [GN * Cc];
__device__ float    g_xr2 [GN * Cc];
__device__ float    g_h2  [GN * Cc];
__device__ int      g_ideg[GN];
__device__ int      g_off [GN + 1];
__device__ int      g_cur [GN];
__device__ int      g_csrc[GE];     // src as global row id (g*Nn+src)
__device__ float    g_cw  [GE];
__device__ float    g_loopsum[GN];
__device__ unsigned g_GvEnc[Cc];
__device__ float    g_gpart[Cc];

// ---------------- helpers ----------------
__device__ __forceinline__ unsigned fenc(float f) {
    unsigned u = __float_as_uint(f);
    return (u & 0x80000000u) ? ~u : (u | 0x80000000u);
}
__device__ __forceinline__ float fdec(unsigned u) {
    return __uint_as_float((u & 0x80000000u) ? (u & 0x7fffffffu) : ~u);
}
__device__ __forceinline__ float wsum(float v) {
    v += __shfl_xor_sync(0xffffffffu, v, 16);
    v += __shfl_xor_sync(0xffffffffu, v, 8);
    v += __shfl_xor_sync(0xffffffffu, v, 4);
    v += __shfl_xor_sync(0xffffffffu, v, 2);
    v += __shfl_xor_sync(0xffffffffu, v, 1);
    return v;
}
__device__ __forceinline__ unsigned f2tf(float f) {
    unsigned r;
    asm("cvt.rna.tf32.f32 %0, %1;" : "=r"(r) : "f"(f));
    return r;
}
__device__ __forceinline__ void mma_tf32(float* c, const unsigned* a, const unsigned* b) {
    asm volatile(
        "mma.sync.aligned.m16n8k8.row.col.f32.tf32.tf32.f32 "
        "{%0,%1,%2,%3}, {%4,%5,%6,%7}, {%8,%9}, {%0,%1,%2,%3};"
        : "+f"(c[0]), "+f"(c[1]), "+f"(c[2]), "+f"(c[3])
        : "r"(a[0]), "r"(a[1]), "r"(a[2]), "r"(a[3]), "r"(b[0]), "r"(b[1]));
}

// ---------------- init ----------------
__global__ void k_init() {
    int i = blockIdx.x * blockDim.x + threadIdx.x;
    if (i < GN) { g_ideg[i] = 0; g_loopsum[i] = 0.f; }
    if (i < Cc) g_GvEnc[i] = MINF_ENC;
}

// ---------------- degree histogram + loop-weight sum ----------------
__global__ void k_count(const int* __restrict__ ei, const float* __restrict__ ew) {
    int i = blockIdx.x * blockDim.x + threadIdx.x;
    if (i >= GE) return;
    int g = i / Ee, e = i - g * Ee;
    int dst = ei[(size_t)g * 2 * Ee + Ee + e];
    atomicAdd(&g_ideg[g * Nn + dst], 1);
    atomicAdd(&g_loopsum[g * Nn + dst], ew[i]);
}

// ---------------- single-block exclusive scan over GN ----------------
__global__ void k_scan() {
    __shared__ int ssum[1024];
    int t = threadIdx.x;
    const int per = (GN + 1023) / 1024;   // 40
    int s = 0;
    for (int i = 0; i < per; i++) {
        int idx = t * per + i;
        if (idx < GN) s += g_ideg[idx];
    }
    ssum[t] = s;
    __syncthreads();
    for (int d = 1; d < 1024; d <<= 1) {
        int v = (t >= d) ? ssum[t - d] : 0;
        __syncthreads();
        ssum[t] += v;
        __syncthreads();
    }
    int run = ssum[t] - s;
    for (int i = 0; i < per; i++) {
        int idx = t * per + i;
        if (idx < GN) {
            g_off[idx] = run;
            g_cur[idx] = run;
            run += g_ideg[idx];
        }
    }
    if (t == 0) g_off[GN] = GE;
}

// ---------------- scatter edges into CSR by dst ----------------
__global__ void k_scatter(const int* __restrict__ ei, const float* __restrict__ ew) {
    int i = blockIdx.x * blockDim.x + threadIdx.x;
    if (i >= GE) return;
    int g = i / Ee, e = i - g * Ee;
    int src = ei[(size_t)g * 2 * Ee + e];
    int dst = ei[(size_t)g * 2 * Ee + Ee + e];
    int pos = atomicAdd(&g_cur[g * Nn + dst], 1);
    g_csrc[pos] = g * Nn + src;
    g_cw[pos] = ew[i];
}

// ---------------- dual-output TF32 tensor-core GEMM --------------------
// Cl = A@Wl+bl, Cr = A@Wr+br; logical columns [0,2N): left half -> Cl.
// BM=128, BN=128, BK=32; 256 threads = 8 warps, warp tile 32x64.
// mma.sync.m16n8k8 tf32. As[m][k] pad->36 (banks 4m+k full-rank),
// Bs[k][n] pad->136 (banks 8k+n full-rank): both conflict-free.
__global__ void sgemm_dual_tf32(const float* __restrict__ A,
                                const float* __restrict__ Wl, const float* __restrict__ Wr,
                                const float* __restrict__ bl, const float* __restrict__ br,
                                float* __restrict__ Cl, float* __restrict__ Cr,
                                int M, int N, int K) {
    __shared__ unsigned As[128][36];
    __shared__ unsigned Bs[32][136];
    int tid = threadIdx.x;
    int lane = tid & 31;
    int wid = tid >> 5;
    int g = lane >> 2, t = lane & 3;
    int m0w = (wid & 3) * 32;     // warp row origin
    int n0w = (wid >> 2) * 64;    // warp col origin
    int bm = blockIdx.y * 128, bn = blockIdx.x * 128;

    float acc[2][8][4];
#pragma unroll
    for (int ms = 0; ms < 2; ms++)
#pragma unroll
        for (int ns = 0; ns < 8; ns++)
#pragma unroll
            for (int i = 0; i < 4; i++) acc[ms][ns][i] = 0.f;

    for (int k0 = 0; k0 < K; k0 += 32) {
        // stage A: 128x32, float4 per quad
#pragma unroll
        for (int i = 0; i < 4; i++) {
            int qid = tid + i * 256;
            int r = qid >> 3, qc = (qid & 7) * 4;
            float4 v = make_float4(0.f, 0.f, 0.f, 0.f);
            if (bm + r < M) v = *(const float4*)(A + (size_t)(bm + r) * K + k0 + qc);
            As[r][qc + 0] = f2tf(v.x);
            As[r][qc + 1] = f2tf(v.y);
            As[r][qc + 2] = f2tf(v.z);
            As[r][qc + 3] = f2tf(v.w);
        }
        // stage B: 32x128 logical cols
#pragma unroll
        for (int i = 0; i < 4; i++) {
            int qid = tid + i * 256;
            int r = qid >> 5, qc = (qid & 31) * 4;
            int cg = bn + qc;
            const float* src = (cg < N) ? (Wl + (size_t)(k0 + r) * N + cg)
                                        : (Wr + (size_t)(k0 + r) * N + cg - N);
            float4 v = *(const float4*)src;
            Bs[r][qc + 0] = f2tf(v.x);
            Bs[r][qc + 1] = f2tf(v.y);
            Bs[r][qc + 2] = f2tf(v.z);
            Bs[r][qc + 3] = f2tf(v.w);
        }
        __syncthreads();
#pragma unroll
        for (int kc = 0; kc < 32; kc += 8) {
            unsigned af[2][4], bf[8][2];
#pragma unroll
            for (int ms = 0; ms < 2; ms++) {
                int mr = m0w + ms * 16 + g;
                af[ms][0] = As[mr][kc + t];
                af[ms][1] = As[mr + 8][kc + t];
                af[ms][2] = As[mr][kc + t + 4];
                af[ms][3] = As[mr + 8][kc + t + 4];
            }
#pragma unroll
            for (int ns = 0; ns < 8; ns++) {
                int nc = n0w + ns * 8 + g;
                bf[ns][0] = Bs[kc + t][nc];
                bf[ns][1] = Bs[kc + t + 4][nc];
            }
#pragma unroll
            for (int ms = 0; ms < 2; ms++)
#pragma unroll
                for (int ns = 0; ns < 8; ns++)
                    mma_tf32(acc[ms][ns], af[ms], bf[ns]);
        }
        __syncthreads();
    }

    // writeback with bias, split Cl/Cr
#pragma unroll
    for (int ms = 0; ms < 2; ms++) {
#pragma unroll
        for (int ns = 0; ns < 8; ns++) {
            int cg = bn + n0w + ns * 8 + t * 2;
            float b0, b1;
            float* Cp;
            int cl;
            if (cg < N) { Cp = Cl; cl = cg; } else { Cp = Cr; cl = cg - N; }
            if (cg < N) { b0 = bl[cl]; b1 = bl[cl + 1]; }
            else        { b0 = br[cl]; b1 = br[cl + 1]; }
            int r0 = bm + m0w + ms * 16 + g;
            if (r0 < M) {
                float2 v = make_float2(acc[ms][ns][0] + b0, acc[ms][ns][1] + b1);
                *(float2*)(Cp + (size_t)r0 * N + cl) = v;
            }
            if (r0 + 8 < M) {
                float2 v = make_float2(acc[ms][ns][2] + b0, acc[ms][ns][3] + b1);
                *(float2*)(Cp + (size_t)(r0 + 8) * N + cl) = v;
            }
        }
    }
}

// ---------------- fused layer-1 attention ----------------
__global__ void k_attn1(const float* __restrict__ We1, const float* __restrict__ att1,
                        const float* __restrict__ bias1) {
    int warp = (blockIdx.x * blockDim.x + threadIdx.x) >> 5;
    int lane = threadIdx.x & 31;
    if (warp >= GN) return;
    int node = warp;
    int base = lane * 16;

    float we[16], at[16], xr[16], acc[16];
    {
        const float4* wep = (const float4*)(We1 + base);
        const float4* atp = (const float4*)(att1 + base);
        const float4* xrp = (const float4*)(g_xr1 + (size_t)node * HC + base);
#pragma unroll
        for (int q = 0; q < 4; q++) {
            float4 a = wep[q]; we[q*4] = a.x; we[q*4+1] = a.y; we[q*4+2] = a.z; we[q*4+3] = a.w;
            float4 b = atp[q]; at[q*4] = b.x; at[q*4+1] = b.y; at[q*4+2] = b.z; at[q*4+3] = b.w;
            float4 c = xrp[q]; xr[q*4] = c.x; xr[q*4+1] = c.y; xr[q*4+2] = c.z; xr[q*4+3] = c.w;
        }
    }
#pragma unroll
    for (int j = 0; j < 16; j++) acc[j] = 0.f;
    float m = -1e30f, den = 0.f;

    int beg = g_off[node], end = g_off[node + 1];
    float wself = g_loopsum[node] / fmaxf((float)(end - beg), 1.f);

    for (int e = beg - 1; e < end; e++) {
        int src; float w;
        if (e < beg) { src = node; w = wself; }
        else         { src = g_csrc[e]; w = g_cw[e]; }
        float xl[16];
        {
            const float4* xlp = (const float4*)(g_xl1 + (size_t)src * HC + base);
#pragma unroll
            for (int q = 0; q < 4; q++) {
                float4 v = xlp[q];
                xl[q*4] = v.x; xl[q*4+1] = v.y; xl[q*4+2] = v.z; xl[q*4+3] = v.w;
            }
        }
        float p = 0.f;
#pragma unroll
        for (int j = 0; j < 16; j++) {
            float v = xl[j] + xr[j] + w * we[j];
            v = v > 0.f ? v : 0.2f * v;
            p = fmaf(v, at[j], p);
        }
        p += __shfl_xor_sync(0xffffffffu, p, 1);
        p += __shfl_xor_sync(0xffffffffu, p, 2);
        if (p > m) {
            float sc = __expf(m - p);
            den = den * sc + 1.f;
#pragma unroll
            for (int j = 0; j < 16; j++) acc[j] = fmaf(acc[j], sc, xl[j]);
            m = p;
        } else {
            float c = __expf(p - m);
            den += c;
#pragma unroll
            for (int j = 0; j < 16; j++) acc[j] = fmaf(xl[j], c, acc[j]);
        }
    }
    float inv = 1.f / den;
    float* o = g_h1 + (size_t)node * HC + base;
    const float* bi = bias1 + base;
#pragma unroll
    for (int j = 0; j < 16; j++) {
        float v = acc[j] * inv + bi[j];
        o[j] = v > 0.f ? v : (__expf(v) - 1.f);
    }
}

// ---------------- fused layer-2 attention (1 head, C=64) ----------------
__global__ void k_attn2(const float* __restrict__ We2, const float* __restrict__ att2,
                        const float* __restrict__ bias2) {
    int warp = (blockIdx.x * blockDim.x + threadIdx.x) >> 5;
    int lane = threadIdx.x & 31;
    if (warp >= GN) return;
    int node = warp;
    int b2 = lane * 2;

    float2 we = *(const float2*)(We2 + b2);
    float2 at = *(const float2*)(att2 + b2);
    float2 xr = *(const float2*)(g_xr2 + (size_t)node * Cc + b2);
    float acc0 = 0.f, acc1 = 0.f, m = -1e30f, den = 0.f;

    int beg = g_off[node], end = g_off[node + 1];
    float wself = g_loopsum[node] / fmaxf((float)(end - beg), 1.f);

    for (int e = beg - 1; e < end; e++) {
        int src; float w;
        if (e < beg) { src = node; w = wself; }
        else         { src = g_csrc[e]; w = g_cw[e]; }
        float2 xl = *(const float2*)(g_xl2 + (size_t)src * Cc + b2);
        float v0 = xl.x + xr.x + w * we.x;
        float v1 = xl.y + xr.y + w * we.y;
        v0 = v0 > 0.f ? v0 : 0.2f * v0;
        v1 = v1 > 0.f ? v1 : 0.2f * v1;
        float p = wsum(fmaf(v0, at.x, v1 * at.y));
        if (p > m) {
            float sc = __expf(m - p);
            den = den * sc + 1.f;
            acc0 = fmaf(acc0, sc, xl.x);
            acc1 = fmaf(acc1, sc, xl.y);
            m = p;
        } else {
            float c = __expf(p - m);
            den += c;
            acc0 = fmaf(xl.x, c, acc0);
            acc1 = fmaf(xl.y, c, acc1);
        }
    }
    float inv = 1.f / den;
    float v0 = acc0 * inv + bias2[b2];
    float v1 = acc1 * inv + bias2[b2 + 1];
    v0 = v0 > 0.f ? v0 : (__expf(v0) - 1.f);
    v1 = v1 > 0.f ? v1 : (__expf(v1) - 1.f);
    float* o = g_h2 + (size_t)node * Cc + b2;
    o[0] = v0; o[1] = v1;
}

// ---------------- global max over all nodes/graphs ----------------
__global__ void k_gmax() {
    int col = threadIdx.x & 63;
    int rg = threadIdx.x >> 6;
    float m = -1e30f;
    for (int row = blockIdx.x * 4 + rg; row < GN; row += gridDim.x * 4)
        m = fmaxf(m, g_h2[(size_t)row * Cc + col]);
    __shared__ float sm[256];
    sm[threadIdx.x] = m;
    __syncthreads();
    if (threadIdx.x < 64) {
        float v = fmaxf(fmaxf(sm[threadIdx.x], sm[threadIdx.x + 64]),
                        fmaxf(sm[threadIdx.x + 128], sm[threadIdx.x + 192]));
        atomicMax(&g_GvEnc[threadIdx.x], fenc(v));
    }
}

// ---------------- graph vector path ----------------
__global__ void k_graphvec(const float* __restrict__ Wg, const float* __restrict__ bg,
                           const float* __restrict__ Wn, const float* __restrict__ bn) {
    __shared__ float sGv[64], sGv2[64];
    int t = threadIdx.x;
    sGv[t] = fdec(g_GvEnc[t]);
    __syncthreads();
    float a = bg[t];
#pragma unroll
    for (int c = 0; c < 64; c++) a = fmaf(sGv[c], Wg[c * 64 + t], a);
    sGv2[t] = fmaxf(a, 0.f);
    __syncthreads();
    float b = bn[t];
#pragma unroll
    for (int c = 0; c < 64; c++) b = fmaf(sGv2[c], Wn[(64 + c) * 64 + t], b);
    g_gpart[t] = b;
}

// ---------------- final node MLP ----------------
__global__ void k_final(const float* __restrict__ Wn, const float* __restrict__ Wo,
                        const float* __restrict__ bo, float* __restrict__ out) {
    __shared__ float sWn[64 * 64];
    __shared__ float sWo[64], sGp[64];
    for (int i = threadIdx.x; i < 64 * 64; i += blockDim.x) sWn[i] = Wn[i];
    if (threadIdx.x < 64) { sWo[threadIdx.x] = Wo[threadIdx.x]; sGp[threadIdx.x] = g_gpart[threadIdx.x]; }
    __syncthreads();
    int lane = threadIdx.x & 31;
    int warp = (blockIdx.x * blockDim.x + threadIdx.x) >> 5;
    int nwarps = (gridDim.x * blockDim.x) >> 5;
    float b0 = bo[0];
    for (int node = warp; node < GN; node += nwarps) {
        const float* row = g_h2 + (size_t)node * Cc;
        float r0 = row[lane], r1 = row[lane + 32];
        float a0 = 0.f, a1 = 0.f;
#pragma unroll
        for (int c = 0; c < 64; c++) {
            float rc = __shfl_sync(0xffffffffu, c < 32 ? r0 : r1, c & 31);
            a0 = fmaf(rc, sWn[c * 64 + lane], a0);
            a1 = fmaf(rc, sWn[c * 64 + lane + 32], a1);
        }
        float t0 = fmaxf(a0 + sGp[lane], 0.f);
        float t1 = fmaxf(a1 + sGp[lane + 32], 0.f);
        float o = wsum(t0 * sWo[lane] + t1 * sWo[lane + 32]);
        if (lane == 0) out[node] = o + b0;
    }
}

// ---------------- launch ----------------
extern "C" void kernel_launch(void* const* d_in, const int* in_sizes, int n_in,
                              void* d_out, int out_size) {
    const float* x     = (const float*)d_in[0];
    const int*   ei    = (const int*)  d_in[1];
    const float* ew    = (const float*)d_in[2];
    const float* Wl1   = (const float*)d_in[3];
    const float* bl1   = (const float*)d_in[4];
    const float* Wr1   = (const float*)d_in[5];
    const float* br1   = (const float*)d_in[6];
    const float* We1   = (const float*)d_in[7];
    const float* att1  = (const float*)d_in[8];
    const float* bias1 = (const float*)d_in[9];
    const float* Wl2   = (const float*)d_in[10];
    const float* bl2   = (const float*)d_in[11];
    const float* Wr2   = (const float*)d_in[12];
    const float* br2   = (const float*)d_in[13];
    const float* We2   = (const float*)d_in[14];
    const float* att2  = (const float*)d_in[15];
    const float* bias2 = (const float*)d_in[16];
    const float* Wg    = (const float*)d_in[17];
    const float* bg    = (const float*)d_in[18];
    const float* Wn    = (const float*)d_in[19];
    const float* bn    = (const float*)d_in[20];
    const float* Wo    = (const float*)d_in[21];
    const float* bo    = (const float*)d_in[22];
    float* out = (float*)d_out;

    float *p_xl1, *p_xr1, *p_h1, *p_xl2, *p_xr2;
    cudaGetSymbolAddress((void**)&p_xl1, g_xl1);
    cudaGetSymbolAddress((void**)&p_xr1, g_xr1);
    cudaGetSymbolAddress((void**)&p_h1,  g_h1);
    cudaGetSymbolAddress((void**)&p_xl2, g_xl2);
    cudaGetSymbolAddress((void**)&p_xr2, g_xr2);

    const int T = 256;
    k_init<<<(GN + T - 1) / T, T>>>();
    k_count<<<(GE + T - 1) / T, T>>>(ei, ew);
    k_scan<<<1, 1024>>>();
    k_scatter<<<(GE + T - 1) / T, T>>>(ei, ew);

    // layer-1 GEMMs: column space 2*512 = 1024 -> grid.x = 8
    sgemm_dual_tf32<<<dim3(8, (GN + 127) / 128), T>>>(x, Wl1, Wr1, bl1, br1,
                                                      p_xl1, p_xr1, GN, HC, Ff);
    k_attn1<<<(GN + 7) / 8, T>>>(We1, att1, bias1);

    // layer-2 GEMMs: column space 2*64 = 128 -> grid.x = 1
    sgemm_dual_tf32<<<dim3(1, (GN + 127) / 128), T>>>(p_h1, Wl2, Wr2, bl2, br2,
                                                      p_xl2, p_xr2, GN, Cc, HC);
    k_attn2<<<(GN + 7) / 8, T>>>(We2, att2, bias2);

    k_gmax<<<148, 256>>>();
    k_graphvec<<<1, 64>>>(Wg, bg, Wn, bn);
    k_final<<<1184, 256>>>(Wn, Wo, bo, out);
}

// round 6
// speedup vs baseline: 2.4554x; 1.2358x over previous
#include <cuda_runtime.h>
#include <cuda_fp16.h>
#include <math.h>

#define Gc   2
#define Nn   20000
#define Ee   160000
#define Ff   128
#define Cc   64
#define Hh   8
#define HC   512
#define GN   (Gc * Nn)      // 40000
#define GE   (Gc * Ee)      // 320000

#define MINF_ENC 0x007FFFFFu   // fenc(-inf)

// ---------------- scratch (device globals; no cudaMalloc allowed) ----------
__device__ __half   g_xl1h[GN * HC];   // fp16 xl (layer 1) - 41MB, L2-resident
__device__ float    g_xr1 [GN * HC];
__device__ float    g_h1  [GN * HC];
__device__ __half   g_xl2h[GN * Cc];   // fp16 xl (layer 2)
__device__ float    g_xr2 [GN * Cc];
__device__ float    g_h2  [GN * Cc];
__device__ int      g_ideg[GN];
__device__ int      g_off [GN + 1];
__device__ int      g_cur [GN];
__device__ int      g_csrc[GE];
__device__ float    g_cw  [GE];
__device__ float    g_loopsum[GN];
__device__ unsigned g_GvEnc[Cc];
__device__ float    g_gpart[Cc];

// ---------------- helpers ----------------
__device__ __forceinline__ unsigned fenc(float f) {
    unsigned u = __float_as_uint(f);
    return (u & 0x80000000u) ? ~u : (u | 0x80000000u);
}
__device__ __forceinline__ float fdec(unsigned u) {
    return __uint_as_float((u & 0x80000000u) ? (u & 0x7fffffffu) : ~u);
}
__device__ __forceinline__ float wsum(float v) {
    v += __shfl_xor_sync(0xffffffffu, v, 16);
    v += __shfl_xor_sync(0xffffffffu, v, 8);
    v += __shfl_xor_sync(0xffffffffu, v, 4);
    v += __shfl_xor_sync(0xffffffffu, v, 2);
    v += __shfl_xor_sync(0xffffffffu, v, 1);
    return v;
}
__device__ __forceinline__ unsigned f2tf(float f) {
    unsigned r;
    asm("cvt.rna.tf32.f32 %0, %1;" : "=r"(r) : "f"(f));
    return r;
}
__device__ __forceinline__ void mma_tf32(float* c, const unsigned* a, const unsigned* b) {
    asm volatile(
        "mma.sync.aligned.m16n8k8.row.col.f32.tf32.tf32.f32 "
        "{%0,%1,%2,%3}, {%4,%5,%6,%7}, {%8,%9}, {%0,%1,%2,%3};"
        : "+f"(c[0]), "+f"(c[1]), "+f"(c[2]), "+f"(c[3])
        : "r"(a[0]), "r"(a[1]), "r"(a[2]), "r"(a[3]), "r"(b[0]), "r"(b[1]));
}
__device__ __forceinline__ void unpack8h(unsigned a, unsigned b, unsigned c, unsigned d, float* o) {
    float2 f;
    f = __half22float2(*(__half2*)&a); o[0] = f.x; o[1] = f.y;
    f = __half22float2(*(__half2*)&b); o[2] = f.x; o[3] = f.y;
    f = __half22float2(*(__half2*)&c); o[4] = f.x; o[5] = f.y;
    f = __half22float2(*(__half2*)&d); o[6] = f.x; o[7] = f.y;
}

// ---------------- init ----------------
__global__ void k_init() {
    int i = blockIdx.x * blockDim.x + threadIdx.x;
    if (i < GN) { g_ideg[i] = 0; g_loopsum[i] = 0.f; }
    if (i < Cc) g_GvEnc[i] = MINF_ENC;
}

// ---------------- degree histogram + loop-weight sum ----------------
__global__ void k_count(const int* __restrict__ ei, const float* __restrict__ ew) {
    int i = blockIdx.x * blockDim.x + threadIdx.x;
    if (i >= GE) return;
    int g = i / Ee, e = i - g * Ee;
    int dst = ei[(size_t)g * 2 * Ee + Ee + e];
    atomicAdd(&g_ideg[g * Nn + dst], 1);
    atomicAdd(&g_loopsum[g * Nn + dst], ew[i]);
}

// ---------------- single-block exclusive scan over GN ----------------
__global__ void k_scan() {
    __shared__ int ssum[1024];
    int t = threadIdx.x;
    const int per = (GN + 1023) / 1024;
    int s = 0;
    for (int i = 0; i < per; i++) {
        int idx = t * per + i;
        if (idx < GN) s += g_ideg[idx];
    }
    ssum[t] = s;
    __syncthreads();
    for (int d = 1; d < 1024; d <<= 1) {
        int v = (t >= d) ? ssum[t - d] : 0;
        __syncthreads();
        ssum[t] += v;
        __syncthreads();
    }
    int run = ssum[t] - s;
    for (int i = 0; i < per; i++) {
        int idx = t * per + i;
        if (idx < GN) {
            g_off[idx] = run;
            g_cur[idx] = run;
            run += g_ideg[idx];
        }
    }
    if (t == 0) g_off[GN] = GE;
}

// ---------------- scatter edges into CSR by dst ----------------
__global__ void k_scatter(const int* __restrict__ ei, const float* __restrict__ ew) {
    int i = blockIdx.x * blockDim.x + threadIdx.x;
    if (i >= GE) return;
    int g = i / Ee, e = i - g * Ee;
    int src = ei[(size_t)g * 2 * Ee + e];
    int dst = ei[(size_t)g * 2 * Ee + Ee + e];
    int pos = atomicAdd(&g_cur[g * Nn + dst], 1);
    g_csrc[pos] = g * Nn + src;
    g_cw[pos] = ew[i];
}

// ---------------- dual-output TF32 GEMM: Cl(f16) = A@Wl+bl, Cr(f32) = A@Wr+br
__global__ void sgemm_dual_tf32(const float* __restrict__ A,
                                const float* __restrict__ Wl, const float* __restrict__ Wr,
                                const float* __restrict__ bl, const float* __restrict__ br,
                                __half* __restrict__ Clh, float* __restrict__ Cr,
                                int M, int N, int K) {
    __shared__ unsigned As[128][36];
    __shared__ unsigned Bs[32][136];
    int tid = threadIdx.x;
    int lane = tid & 31;
    int wid = tid >> 5;
    int g = lane >> 2, t = lane & 3;
    int m0w = (wid & 3) * 32;
    int n0w = (wid >> 2) * 64;
    int bm = blockIdx.y * 128, bn = blockIdx.x * 128;

    float acc[2][8][4];
#pragma unroll
    for (int ms = 0; ms < 2; ms++)
#pragma unroll
        for (int ns = 0; ns < 8; ns++)
#pragma unroll
            for (int i = 0; i < 4; i++) acc[ms][ns][i] = 0.f;

    for (int k0 = 0; k0 < K; k0 += 32) {
#pragma unroll
        for (int i = 0; i < 4; i++) {
            int qid = tid + i * 256;
            int r = qid >> 3, qc = (qid & 7) * 4;
            float4 v = make_float4(0.f, 0.f, 0.f, 0.f);
            if (bm + r < M) v = *(const float4*)(A + (size_t)(bm + r) * K + k0 + qc);
            As[r][qc + 0] = f2tf(v.x);
            As[r][qc + 1] = f2tf(v.y);
            As[r][qc + 2] = f2tf(v.z);
            As[r][qc + 3] = f2tf(v.w);
        }
#pragma unroll
        for (int i = 0; i < 4; i++) {
            int qid = tid + i * 256;
            int r = qid >> 5, qc = (qid & 31) * 4;
            int cg = bn + qc;
            const float* src = (cg < N) ? (Wl + (size_t)(k0 + r) * N + cg)
                                        : (Wr + (size_t)(k0 + r) * N + cg - N);
            float4 v = *(const float4*)src;
            Bs[r][qc + 0] = f2tf(v.x);
            Bs[r][qc + 1] = f2tf(v.y);
            Bs[r][qc + 2] = f2tf(v.z);
            Bs[r][qc + 3] = f2tf(v.w);
        }
        __syncthreads();
#pragma unroll
        for (int kc = 0; kc < 32; kc += 8) {
            unsigned af[2][4], bf[8][2];
#pragma unroll
            for (int ms = 0; ms < 2; ms++) {
                int mr = m0w + ms * 16 + g;
                af[ms][0] = As[mr][kc + t];
                af[ms][1] = As[mr + 8][kc + t];
                af[ms][2] = As[mr][kc + t + 4];
                af[ms][3] = As[mr + 8][kc + t + 4];
            }
#pragma unroll
            for (int ns = 0; ns < 8; ns++) {
                int nc = n0w + ns * 8 + g;
                bf[ns][0] = Bs[kc + t][nc];
                bf[ns][1] = Bs[kc + t + 4][nc];
            }
#pragma unroll
            for (int ms = 0; ms < 2; ms++)
#pragma unroll
                for (int ns = 0; ns < 8; ns++)
                    mma_tf32(acc[ms][ns], af[ms], bf[ns]);
        }
        __syncthreads();
    }

#pragma unroll
    for (int ms = 0; ms < 2; ms++) {
#pragma unroll
        for (int ns = 0; ns < 8; ns++) {
            int cg = bn + n0w + ns * 8 + t * 2;
            int r0 = bm + m0w + ms * 16 + g;
            if (cg < N) {
                float b0 = bl[cg], b1 = bl[cg + 1];
                if (r0 < M) {
                    __half2 v = __floats2half2_rn(acc[ms][ns][0] + b0, acc[ms][ns][1] + b1);
                    *(__half2*)(Clh + (size_t)r0 * N + cg) = v;
                }
                if (r0 + 8 < M) {
                    __half2 v = __floats2half2_rn(acc[ms][ns][2] + b0, acc[ms][ns][3] + b1);
                    *(__half2*)(Clh + (size_t)(r0 + 8) * N + cg) = v;
                }
            } else {
                int cl = cg - N;
                float b0 = br[cl], b1 = br[cl + 1];
                if (r0 < M) {
                    float2 v = make_float2(acc[ms][ns][0] + b0, acc[ms][ns][1] + b1);
                    *(float2*)(Cr + (size_t)r0 * N + cl) = v;
                }
                if (r0 + 8 < M) {
                    float2 v = make_float2(acc[ms][ns][2] + b0, acc[ms][ns][3] + b1);
                    *(float2*)(Cr + (size_t)(r0 + 8) * N + cl) = v;
                }
            }
        }
    }
}

// ---------------- fused layer-1 attention (fp16 xl) ----------------
__global__ void k_attn1(const float* __restrict__ We1, const float* __restrict__ att1,
                        const float* __restrict__ bias1) {
    int warp = (blockIdx.x * blockDim.x + threadIdx.x) >> 5;
    int lane = threadIdx.x & 31;
    if (warp >= GN) return;
    int node = warp;
    int base = lane * 16;

    float we[16], at[16], xr[16], acc[16];
    {
        const float4* wep = (const float4*)(We1 + base);
        const float4* atp = (const float4*)(att1 + base);
        const float4* xrp = (const float4*)(g_xr1 + (size_t)node * HC + base);
#pragma unroll
        for (int q = 0; q < 4; q++) {
            float4 a = wep[q]; we[q*4] = a.x; we[q*4+1] = a.y; we[q*4+2] = a.z; we[q*4+3] = a.w;
            float4 b = atp[q]; at[q*4] = b.x; at[q*4+1] = b.y; at[q*4+2] = b.z; at[q*4+3] = b.w;
            float4 c = xrp[q]; xr[q*4] = c.x; xr[q*4+1] = c.y; xr[q*4+2] = c.z; xr[q*4+3] = c.w;
        }
    }
#pragma unroll
    for (int j = 0; j < 16; j++) acc[j] = 0.f;
    float m = -1e30f, den = 0.f;

    int beg = g_off[node], end = g_off[node + 1];
    float wself = g_loopsum[node] / fmaxf((float)(end - beg), 1.f);

    for (int e = beg - 1; e < end; e++) {
        int src; float w;
        if (e < beg) { src = node; w = wself; }
        else         { src = g_csrc[e]; w = g_cw[e]; }
        float xl[16];
        {
            const uint4* xlp = (const uint4*)(g_xl1h + (size_t)src * HC + base);
            uint4 u0 = xlp[0], u1 = xlp[1];
            unpack8h(u0.x, u0.y, u0.z, u0.w, xl);
            unpack8h(u1.x, u1.y, u1.z, u1.w, xl + 8);
        }
        float p = 0.f;
#pragma unroll
        for (int j = 0; j < 16; j++) {
            float v = xl[j] + xr[j] + w * we[j];
            v = v > 0.f ? v : 0.2f * v;
            p = fmaf(v, at[j], p);
        }
        p += __shfl_xor_sync(0xffffffffu, p, 1);
        p += __shfl_xor_sync(0xffffffffu, p, 2);
        if (p > m) {
            float sc = __expf(m - p);
            den = den * sc + 1.f;
#pragma unroll
            for (int j = 0; j < 16; j++) acc[j] = fmaf(acc[j], sc, xl[j]);
            m = p;
        } else {
            float c = __expf(p - m);
            den += c;
#pragma unroll
            for (int j = 0; j < 16; j++) acc[j] = fmaf(xl[j], c, acc[j]);
        }
    }
    float inv = 1.f / den;
    float* o = g_h1 + (size_t)node * HC + base;
    const float* bi = bias1 + base;
#pragma unroll
    for (int j = 0; j < 16; j++) {
        float v = acc[j] * inv + bi[j];
        o[j] = v > 0.f ? v : (__expf(v) - 1.f);
    }
}

// ---------------- fused layer-2 attention (1 head, C=64, fp16 xl) ----------
__global__ void k_attn2(const float* __restrict__ We2, const float* __restrict__ att2,
                        const float* __restrict__ bias2) {
    int warp = (blockIdx.x * blockDim.x + threadIdx.x) >> 5;
    int lane = threadIdx.x & 31;
    if (warp >= GN) return;
    int node = warp;
    int b2 = lane * 2;

    float2 we = *(const float2*)(We2 + b2);
    float2 at = *(const float2*)(att2 + b2);
    float2 xr = *(const float2*)(g_xr2 + (size_t)node * Cc + b2);
    float acc0 = 0.f, acc1 = 0.f, m = -1e30f, den = 0.f;

    int beg = g_off[node], end = g_off[node + 1];
    float wself = g_loopsum[node] / fmaxf((float)(end - beg), 1.f);

    for (int e = beg - 1; e < end; e++) {
        int src; float w;
        if (e < beg) { src = node; w = wself; }
        else         { src = g_csrc[e]; w = g_cw[e]; }
        float2 xl = __half22float2(*(const __half2*)(g_xl2h + (size_t)src * Cc + b2));
        float v0 = xl.x + xr.x + w * we.x;
        float v1 = xl.y + xr.y + w * we.y;
        v0 = v0 > 0.f ? v0 : 0.2f * v0;
        v1 = v1 > 0.f ? v1 : 0.2f * v1;
        float p = wsum(fmaf(v0, at.x, v1 * at.y));
        if (p > m) {
            float sc = __expf(m - p);
            den = den * sc + 1.f;
            acc0 = fmaf(acc0, sc, xl.x);
            acc1 = fmaf(acc1, sc, xl.y);
            m = p;
        } else {
            float c = __expf(p - m);
            den += c;
            acc0 = fmaf(xl.x, c, acc0);
            acc1 = fmaf(xl.y, c, acc1);
        }
    }
    float inv = 1.f / den;
    float v0 = acc0 * inv + bias2[b2];
    float v1 = acc1 * inv + bias2[b2 + 1];
    v0 = v0 > 0.f ? v0 : (__expf(v0) - 1.f);
    v1 = v1 > 0.f ? v1 : (__expf(v1) - 1.f);
    float* o = g_h2 + (size_t)node * Cc + b2;
    o[0] = v0; o[1] = v1;
}

// ---------------- global max over all nodes/graphs ----------------
__global__ void k_gmax() {
    int col = threadIdx.x & 63;
    int rg = threadIdx.x >> 6;
    float m = -1e30f;
    for (int row = blockIdx.x * 4 + rg; row < GN; row += gridDim.x * 4)
        m = fmaxf(m, g_h2[(size_t)row * Cc + col]);
    __shared__ float sm[256];
    sm[threadIdx.x] = m;
    __syncthreads();
    if (threadIdx.x < 64) {
        float v = fmaxf(fmaxf(sm[threadIdx.x], sm[threadIdx.x + 64]),
                        fmaxf(sm[threadIdx.x + 128], sm[threadIdx.x + 192]));
        atomicMax(&g_GvEnc[threadIdx.x], fenc(v));
    }
}

// ---------------- graph vector path ----------------
__global__ void k_graphvec(const float* __restrict__ Wg, const float* __restrict__ bg,
                           const float* __restrict__ Wn, const float* __restrict__ bn) {
    __shared__ float sGv[64], sGv2[64];
    int t = threadIdx.x;
    sGv[t] = fdec(g_GvEnc[t]);
    __syncthreads();
    float a = bg[t];
#pragma unroll
    for (int c = 0; c < 64; c++) a = fmaf(sGv[c], Wg[c * 64 + t], a);
    sGv2[t] = fmaxf(a, 0.f);
    __syncthreads();
    float b = bn[t];
#pragma unroll
    for (int c = 0; c < 64; c++) b = fmaf(sGv2[c], Wn[(64 + c) * 64 + t], b);
    g_gpart[t] = b;
}

// ---------------- final node MLP ----------------
__global__ void k_final(const float* __restrict__ Wn, const float* __restrict__ Wo,
                        const float* __restrict__ bo, float* __restrict__ out) {
    __shared__ float sWn[64 * 64];
    __shared__ float sWo[64], sGp[64];
    for (int i = threadIdx.x; i < 64 * 64; i += blockDim.x) sWn[i] = Wn[i];
    if (threadIdx.x < 64) { sWo[threadIdx.x] = Wo[threadIdx.x]; sGp[threadIdx.x] = g_gpart[threadIdx.x]; }
    __syncthreads();
    int lane = threadIdx.x & 31;
    int warp = (blockIdx.x * blockDim.x + threadIdx.x) >> 5;
    int nwarps = (gridDim.x * blockDim.x) >> 5;
    float b0 = bo[0];
    for (int node = warp; node < GN; node += nwarps) {
        const float* row = g_h2 + (size_t)node * Cc;
        float r0 = row[lane], r1 = row[lane + 32];
        float a0 = 0.f, a1 = 0.f;
#pragma unroll
        for (int c = 0; c < 64; c++) {
            float rc = __shfl_sync(0xffffffffu, c < 32 ? r0 : r1, c & 31);
            a0 = fmaf(rc, sWn[c * 64 + lane], a0);
            a1 = fmaf(rc, sWn[c * 64 + lane + 32], a1);
        }
        float t0 = fmaxf(a0 + sGp[lane], 0.f);
        float t1 = fmaxf(a1 + sGp[lane + 32], 0.f);
        float o = wsum(t0 * sWo[lane] + t1 * sWo[lane + 32]);
        if (lane == 0) out[node] = o + b0;
    }
}

// ---------------- launch ----------------
extern "C" void kernel_launch(void* const* d_in, const int* in_sizes, int n_in,
                              void* d_out, int out_size) {
    const float* x     = (const float*)d_in[0];
    const int*   ei    = (const int*)  d_in[1];
    const float* ew    = (const float*)d_in[2];
    const float* Wl1   = (const float*)d_in[3];
    const float* bl1   = (const float*)d_in[4];
    const float* Wr1   = (const float*)d_in[5];
    const float* br1   = (const float*)d_in[6];
    const float* We1   = (const float*)d_in[7];
    const float* att1  = (const float*)d_in[8];
    const float* bias1 = (const float*)d_in[9];
    const float* Wl2   = (const float*)d_in[10];
    const float* bl2   = (const float*)d_in[11];
    const float* Wr2   = (const float*)d_in[12];
    const float* br2   = (const float*)d_in[13];
    const float* We2   = (const float*)d_in[14];
    const float* att2  = (const float*)d_in[15];
    const float* bias2 = (const float*)d_in[16];
    const float* Wg    = (const float*)d_in[17];
    const float* bg    = (const float*)d_in[18];
    const float* Wn    = (const float*)d_in[19];
    const float* bn    = (const float*)d_in[20];
    const float* Wo    = (const float*)d_in[21];
    const float* bo    = (const float*)d_in[22];
    float* out = (float*)d_out;

    __half *p_xl1h, *p_xl2h;
    float *p_xr1, *p_h1, *p_xr2;
    cudaGetSymbolAddress((void**)&p_xl1h, g_xl1h);
    cudaGetSymbolAddress((void**)&p_xr1,  g_xr1);
    cudaGetSymbolAddress((void**)&p_h1,   g_h1);
    cudaGetSymbolAddress((void**)&p_xl2h, g_xl2h);
    cudaGetSymbolAddress((void**)&p_xr2,  g_xr2);

    const int T = 256;
    k_init<<<(GN + T - 1) / T, T>>>();
    k_count<<<(GE + T - 1) / T, T>>>(ei, ew);
    k_scan<<<1, 1024>>>();
    k_scatter<<<(GE + T - 1) / T, T>>>(ei, ew);

    // layer-1 GEMMs: column space 2*512 = 1024 -> grid.x = 8
    sgemm_dual_tf32<<<dim3(8, (GN + 127) / 128), T>>>(x, Wl1, Wr1, bl1, br1,
                                                      p_xl1h, p_xr1, GN, HC, Ff);
    k_attn1<<<(GN + 7) / 8, T>>>(We1, att1, bias1);

    // layer-2 GEMMs: column space 2*64 = 128 -> grid.x = 1
    sgemm_dual_tf32<<<dim3(1, (GN + 127) / 128), T>>>(p_h1, Wl2, Wr2, bl2, br2,
                                                      p_xl2h, p_xr2, GN, Cc, HC);
    k_attn2<<<(GN + 7) / 8, T>>>(We2, att2, bias2);

    k_gmax<<<148, 256>>>();
    k_graphvec<<<1, 64>>>(Wg, bg, Wn, bn);
    k_final<<<1184, 256>>>(Wn, Wo, bo, out);
}

// round 7
// speedup vs baseline: 2.9036x; 1.1825x over previous
#include <cuda_runtime.h>
#include <cuda_fp16.h>
#include <math.h>

#define Gc   2
#define Nn   20000
#define Ee   160000
#define Ff   128
#define Cc   64
#define Hh   8
#define HC   512
#define GN   (Gc * Nn)      // 40000
#define GE   (Gc * Ee)      // 320000

#define MINF_ENC 0x007FFFFFu   // fenc(-inf)

// ---------------- scratch (device globals; no cudaMalloc allowed) ----------
__device__ __half   g_xh  [GN * Ff];    // x in half
__device__ __half   g_w1t [1024 * 128]; // [Wl1|Wr1] transposed [n][k] half
__device__ __half   g_w2t [128 * 512];  // [Wl2|Wr2] transposed [n][k] half
__device__ __half   g_xl1h[GN * HC];    // fp16 xl (layer 1) - 41MB, L2-resident
__device__ float    g_xr1 [GN * HC];
__device__ __half   g_h1h [GN * HC];    // h1 in half (GEMM2 input)
__device__ __half   g_xl2h[GN * Cc];
__device__ float    g_xr2 [GN * Cc];
__device__ float    g_h2  [GN * Cc];
__device__ int      g_ideg[GN];
__device__ int      g_off [GN + 1];
__device__ int      g_cur [GN];
__device__ int      g_csrc[GE];
__device__ float    g_cw  [GE];
__device__ float    g_loopsum[GN];
__device__ unsigned g_GvEnc[Cc];
__device__ float    g_gpart[Cc];

// ---------------- helpers ----------------
__device__ __forceinline__ unsigned fenc(float f) {
    unsigned u = __float_as_uint(f);
    return (u & 0x80000000u) ? ~u : (u | 0x80000000u);
}
__device__ __forceinline__ float fdec(unsigned u) {
    return __uint_as_float((u & 0x80000000u) ? (u & 0x7fffffffu) : ~u);
}
__device__ __forceinline__ float wsum(float v) {
    v += __shfl_xor_sync(0xffffffffu, v, 16);
    v += __shfl_xor_sync(0xffffffffu, v, 8);
    v += __shfl_xor_sync(0xffffffffu, v, 4);
    v += __shfl_xor_sync(0xffffffffu, v, 2);
    v += __shfl_xor_sync(0xffffffffu, v, 1);
    return v;
}
__device__ __forceinline__ void mma_f16(float* c, const unsigned* a, const unsigned* b) {
    asm volatile(
        "mma.sync.aligned.m16n8k16.row.col.f32.f16.f16.f32 "
        "{%0,%1,%2,%3}, {%4,%5,%6,%7}, {%8,%9}, {%0,%1,%2,%3};"
        : "+f"(c[0]), "+f"(c[1]), "+f"(c[2]), "+f"(c[3])
        : "r"(a[0]), "r"(a[1]), "r"(a[2]), "r"(a[3]), "r"(b[0]), "r"(b[1]));
}
__device__ __forceinline__ void unpack8h(unsigned a, unsigned b, unsigned c, unsigned d, float* o) {
    float2 f;
    f = __half22float2(*(__half2*)&a); o[0] = f.x; o[1] = f.y;
    f = __half22float2(*(__half2*)&b); o[2] = f.x; o[3] = f.y;
    f = __half22float2(*(__half2*)&c); o[4] = f.x; o[5] = f.y;
    f = __half22float2(*(__half2*)&d); o[6] = f.x; o[7] = f.y;
}

// ---------------- init ----------------
__global__ void k_init() {
    int i = blockIdx.x * blockDim.x + threadIdx.x;
    if (i < GN) { g_ideg[i] = 0; g_loopsum[i] = 0.f; }
    if (i < Cc) g_GvEnc[i] = MINF_ENC;
}

// ---------------- half conversions / weight transposes ----------------
__global__ void k_cvtx(const float* __restrict__ x) {
    int i = blockIdx.x * blockDim.x + threadIdx.x;
    if (i < GN * Ff) g_xh[i] = __float2half(x[i]);
}
__global__ void k_cvtw1(const float* __restrict__ Wl1, const float* __restrict__ Wr1) {
    int i = blockIdx.x * blockDim.x + threadIdx.x;
    if (i >= 1024 * 128) return;
    int n = i >> 7, k = i & 127;
    float v = (n < 512) ? Wl1[k * 512 + n] : Wr1[k * 512 + (n - 512)];
    g_w1t[i] = __float2half(v);
}
__global__ void k_cvtw2(const float* __restrict__ Wl2, const float* __restrict__ Wr2) {
    int i = blockIdx.x * blockDim.x + threadIdx.x;
    if (i >= 128 * 512) return;
    int n = i >> 9, k = i & 511;
    float v = (n < 64) ? Wl2[k * 64 + n] : Wr2[k * 64 + (n - 64)];
    g_w2t[i] = __float2half(v);
}

// ---------------- degree histogram + loop-weight sum ----------------
__global__ void k_count(const int* __restrict__ ei, const float* __restrict__ ew) {
    int i = blockIdx.x * blockDim.x + threadIdx.x;
    if (i >= GE) return;
    int g = i / Ee, e = i - g * Ee;
    int dst = ei[(size_t)g * 2 * Ee + Ee + e];
    atomicAdd(&g_ideg[g * Nn + dst], 1);
    atomicAdd(&g_loopsum[g * Nn + dst], ew[i]);
}

// ---------------- single-block exclusive scan over GN ----------------
__global__ void k_scan() {
    __shared__ int ssum[1024];
    int t = threadIdx.x;
    const int per = (GN + 1023) / 1024;
    int s = 0;
    for (int i = 0; i < per; i++) {
        int idx = t * per + i;
        if (idx < GN) s += g_ideg[idx];
    }
    ssum[t] = s;
    __syncthreads();
    for (int d = 1; d < 1024; d <<= 1) {
        int v = (t >= d) ? ssum[t - d] : 0;
        __syncthreads();
        ssum[t] += v;
        __syncthreads();
    }
    int run = ssum[t] - s;
    for (int i = 0; i < per; i++) {
        int idx = t * per + i;
        if (idx < GN) {
            g_off[idx] = run;
            g_cur[idx] = run;
            run += g_ideg[idx];
        }
    }
    if (t == 0) g_off[GN] = GE;
}

// ---------------- scatter edges into CSR by dst ----------------
__global__ void k_scatter(const int* __restrict__ ei, const float* __restrict__ ew) {
    int i = blockIdx.x * blockDim.x + threadIdx.x;
    if (i >= GE) return;
    int g = i / Ee, e = i - g * Ee;
    int src = ei[(size_t)g * 2 * Ee + e];
    int dst = ei[(size_t)g * 2 * Ee + Ee + e];
    int pos = atomicAdd(&g_cur[g * Nn + dst], 1);
    g_csrc[pos] = g * Nn + src;
    g_cw[pos] = ew[i];
}

// ---------------- dual-output fp16 tensor-core GEMM --------------------
// A: [M][K] half row-major. Wt: [2N][K] half row-major (pre-transposed).
// Cl(half) = A@Wl+bl (cols [0,N)), Cr(float) = A@Wr+br (cols [N,2N)).
// BM=128, BN=128, BK=32; 256 threads = 8 warps, warp tile 32x64.
// mma.m16n8k16 f16 with f32 accum. Register double buffering on staging.
__global__ void hgemm_dual(const __half* __restrict__ A,
                           const __half* __restrict__ Wt,
                           const float* __restrict__ bl, const float* __restrict__ br,
                           __half* __restrict__ Clh, float* __restrict__ Cr,
                           int M, int N, int K) {
    // row stride 20 uints = 80B (16B-aligned rows, bank-conflict-free frags)
    __shared__ unsigned As2[128][20];
    __shared__ unsigned Bs2[128][20];
    int tid = threadIdx.x;
    int lane = tid & 31;
    int wid = tid >> 5;
    int g = lane >> 2, t = lane & 3;
    int m0w = (wid & 3) * 32;
    int n0w = (wid >> 2) * 64;
    int bm = blockIdx.y * 128, bn = blockIdx.x * 128;

    float acc[2][8][4];
#pragma unroll
    for (int ms = 0; ms < 2; ms++)
#pragma unroll
        for (int ns = 0; ns < 8; ns++)
#pragma unroll
            for (int i = 0; i < 4; i++) acc[ms][ns][i] = 0.f;

    // staging: tile is 128 rows x 32 halves = 512 uint4; 2 uint4 per thread
    uint4 aST[2], bST[2];

    auto loadG = [&](int k0, uint4* ar, uint4* br_) {
#pragma unroll
        for (int i = 0; i < 2; i++) {
            int qid = tid + i * 256;
            int r = qid >> 2, c = qid & 3;
            uint4 v = make_uint4(0u, 0u, 0u, 0u);
            if (bm + r < M) v = *(const uint4*)(A + (size_t)(bm + r) * K + k0 + c * 8);
            ar[i] = v;
            br_[i] = *(const uint4*)(Wt + (size_t)(bn + r) * K + k0 + c * 8);
        }
    };
    auto stage = [&](const uint4* ar, const uint4* br_) {
#pragma unroll
        for (int i = 0; i < 2; i++) {
            int qid = tid + i * 256;
            int r = qid >> 2, c = qid & 3;
            *(uint4*)&As2[r][c * 4] = ar[i];
            *(uint4*)&Bs2[r][c * 4] = br_[i];
        }
    };

    loadG(0, aST, bST);
    stage(aST, bST);
    __syncthreads();

    for (int k0 = 0; k0 < K; k0 += 32) {
        uint4 aNX[2], bNX[2];
        bool more = (k0 + 32 < K);
        if (more) loadG(k0 + 32, aNX, bNX);

#pragma unroll
        for (int kc = 0; kc < 32; kc += 16) {
            int kw = kc >> 1;
            unsigned af[2][4], bf[8][2];
#pragma unroll
            for (int ms = 0; ms < 2; ms++) {
                int mr = m0w + ms * 16 + g;
                af[ms][0] = As2[mr][kw + t];
                af[ms][1] = As2[mr + 8][kw + t];
                af[ms][2] = As2[mr][kw + t + 4];
                af[ms][3] = As2[mr + 8][kw + t + 4];
            }
#pragma unroll
            for (int ns = 0; ns < 8; ns++) {
                int nc = n0w + ns * 8 + g;
                bf[ns][0] = Bs2[nc][kw + t];
                bf[ns][1] = Bs2[nc][kw + t + 4];
            }
#pragma unroll
            for (int ms = 0; ms < 2; ms++)
#pragma unroll
                for (int ns = 0; ns < 8; ns++)
                    mma_f16(acc[ms][ns], af[ms], bf[ns]);
        }

        if (more) {
            __syncthreads();
            stage(aNX, bNX);
            __syncthreads();
        }
    }

    // writeback with bias, split Cl(half)/Cr(float)
#pragma unroll
    for (int ms = 0; ms < 2; ms++) {
#pragma unroll
        for (int ns = 0; ns < 8; ns++) {
            int cg = bn + n0w + ns * 8 + t * 2;
            int r0 = bm + m0w + ms * 16 + g;
            if (cg < N) {
                float b0 = bl[cg], b1 = bl[cg + 1];
                if (r0 < M) {
                    __half2 v = __floats2half2_rn(acc[ms][ns][0] + b0, acc[ms][ns][1] + b1);
                    *(__half2*)(Clh + (size_t)r0 * N + cg) = v;
                }
                if (r0 + 8 < M) {
                    __half2 v = __floats2half2_rn(acc[ms][ns][2] + b0, acc[ms][ns][3] + b1);
                    *(__half2*)(Clh + (size_t)(r0 + 8) * N + cg) = v;
                }
            } else {
                int cl = cg - N;
                float b0 = br[cl], b1 = br[cl + 1];
                if (r0 < M) {
                    float2 v = make_float2(acc[ms][ns][0] + b0, acc[ms][ns][1] + b1);
                    *(float2*)(Cr + (size_t)r0 * N + cl) = v;
                }
                if (r0 + 8 < M) {
                    float2 v = make_float2(acc[ms][ns][2] + b0, acc[ms][ns][3] + b1);
                    *(float2*)(Cr + (size_t)(r0 + 8) * N + cl) = v;
                }
            }
        }
    }
}

// ---------------- fused layer-1 attention (fp16 xl, half h1 out) ----------
__global__ void k_attn1(const float* __restrict__ We1, const float* __restrict__ att1,
                        const float* __restrict__ bias1) {
    int warp = (blockIdx.x * blockDim.x + threadIdx.x) >> 5;
    int lane = threadIdx.x & 31;
    if (warp >= GN) return;
    int node = warp;
    int base = lane * 16;

    float we[16], at[16], xr[16], acc[16];
    {
        const float4* wep = (const float4*)(We1 + base);
        const float4* atp = (const float4*)(att1 + base);
        const float4* xrp = (const float4*)(g_xr1 + (size_t)node * HC + base);
#pragma unroll
        for (int q = 0; q < 4; q++) {
            float4 a = wep[q]; we[q*4] = a.x; we[q*4+1] = a.y; we[q*4+2] = a.z; we[q*4+3] = a.w;
            float4 b = atp[q]; at[q*4] = b.x; at[q*4+1] = b.y; at[q*4+2] = b.z; at[q*4+3] = b.w;
            float4 c = xrp[q]; xr[q*4] = c.x; xr[q*4+1] = c.y; xr[q*4+2] = c.z; xr[q*4+3] = c.w;
        }
    }
#pragma unroll
    for (int j = 0; j < 16; j++) acc[j] = 0.f;
    float m = -1e30f, den = 0.f;

    int beg = g_off[node], end = g_off[node + 1];
    float wself = g_loopsum[node] / fmaxf((float)(end - beg), 1.f);

    for (int e = beg - 1; e < end; e++) {
        int src; float w;
        if (e < beg) { src = node; w = wself; }
        else         { src = g_csrc[e]; w = g_cw[e]; }
        float xl[16];
        {
            const uint4* xlp = (const uint4*)(g_xl1h + (size_t)src * HC + base);
            uint4 u0 = xlp[0], u1 = xlp[1];
            unpack8h(u0.x, u0.y, u0.z, u0.w, xl);
            unpack8h(u1.x, u1.y, u1.z, u1.w, xl + 8);
        }
        float p = 0.f;
#pragma unroll
        for (int j = 0; j < 16; j++) {
            float v = xl[j] + xr[j] + w * we[j];
            v = v > 0.f ? v : 0.2f * v;
            p = fmaf(v, at[j], p);
        }
        p += __shfl_xor_sync(0xffffffffu, p, 1);
        p += __shfl_xor_sync(0xffffffffu, p, 2);
        if (p > m) {
            float sc = __expf(m - p);
            den = den * sc + 1.f;
#pragma unroll
            for (int j = 0; j < 16; j++) acc[j] = fmaf(acc[j], sc, xl[j]);
            m = p;
        } else {
            float c = __expf(p - m);
            den += c;
#pragma unroll
            for (int j = 0; j < 16; j++) acc[j] = fmaf(xl[j], c, acc[j]);
        }
    }
    float inv = 1.f / den;
    __half* o = g_h1h + (size_t)node * HC + base;
    const float* bi = bias1 + base;
#pragma unroll
    for (int q = 0; q < 8; q++) {
        float v0 = acc[2*q]     * inv + bi[2*q];
        float v1 = acc[2*q + 1] * inv + bi[2*q + 1];
        v0 = v0 > 0.f ? v0 : (__expf(v0) - 1.f);
        v1 = v1 > 0.f ? v1 : (__expf(v1) - 1.f);
        *(__half2*)(o + 2*q) = __floats2half2_rn(v0, v1);
    }
}

// ---------------- fused layer-2 attention (1 head, C=64, fp16 xl) ----------
__global__ void k_attn2(const float* __restrict__ We2, const float* __restrict__ att2,
                        const float* __restrict__ bias2) {
    int warp = (blockIdx.x * blockDim.x + threadIdx.x) >> 5;
    int lane = threadIdx.x & 31;
    if (warp >= GN) return;
    int node = warp;
    int b2 = lane * 2;

    float2 we = *(const float2*)(We2 + b2);
    float2 at = *(const float2*)(att2 + b2);
    float2 xr = *(const float2*)(g_xr2 + (size_t)node * Cc + b2);
    float acc0 = 0.f, acc1 = 0.f, m = -1e30f, den = 0.f;

    int beg = g_off[node], end = g_off[node + 1];
    float wself = g_loopsum[node] / fmaxf((float)(end - beg), 1.f);

    for (int e = beg - 1; e < end; e++) {
        int src; float w;
        if (e < beg) { src = node; w = wself; }
        else         { src = g_csrc[e]; w = g_cw[e]; }
        float2 xl = __half22float2(*(const __half2*)(g_xl2h + (size_t)src * Cc + b2));
        float v0 = xl.x + xr.x + w * we.x;
        float v1 = xl.y + xr.y + w * we.y;
        v0 = v0 > 0.f ? v0 : 0.2f * v0;
        v1 = v1 > 0.f ? v1 : 0.2f * v1;
        float p = wsum(fmaf(v0, at.x, v1 * at.y));
        if (p > m) {
            float sc = __expf(m - p);
            den = den * sc + 1.f;
            acc0 = fmaf(acc0, sc, xl.x);
            acc1 = fmaf(acc1, sc, xl.y);
            m = p;
        } else {
            float c = __expf(p - m);
            den += c;
            acc0 = fmaf(xl.x, c, acc0);
            acc1 = fmaf(xl.y, c, acc1);
        }
    }
    float inv = 1.f / den;
    float v0 = acc0 * inv + bias2[b2];
    float v1 = acc1 * inv + bias2[b2 + 1];
    v0 = v0 > 0.f ? v0 : (__expf(v0) - 1.f);
    v1 = v1 > 0.f ? v1 : (__expf(v1) - 1.f);
    float* o = g_h2 + (size_t)node * Cc + b2;
    o[0] = v0; o[1] = v1;
}

// ---------------- global max over all nodes/graphs ----------------
__global__ void k_gmax() {
    int col = threadIdx.x & 63;
    int rg = threadIdx.x >> 6;
    float m = -1e30f;
    for (int row = blockIdx.x * 4 + rg; row < GN; row += gridDim.x * 4)
        m = fmaxf(m, g_h2[(size_t)row * Cc + col]);
    __shared__ float sm[256];
    sm[threadIdx.x] = m;
    __syncthreads();
    if (threadIdx.x < 64) {
        float v = fmaxf(fmaxf(sm[threadIdx.x], sm[threadIdx.x + 64]),
                        fmaxf(sm[threadIdx.x + 128], sm[threadIdx.x + 192]));
        atomicMax(&g_GvEnc[threadIdx.x], fenc(v));
    }
}

// ---------------- graph vector path ----------------
__global__ void k_graphvec(const float* __restrict__ Wg, const float* __restrict__ bg,
                           const float* __restrict__ Wn, const float* __restrict__ bn) {
    __shared__ float sGv[64], sGv2[64];
    int t = threadIdx.x;
    sGv[t] = fdec(g_GvEnc[t]);
    __syncthreads();
    float a = bg[t];
#pragma unroll
    for (int c = 0; c < 64; c++) a = fmaf(sGv[c], Wg[c * 64 + t], a);
    sGv2[t] = fmaxf(a, 0.f);
    __syncthreads();
    float b = bn[t];
#pragma unroll
    for (int c = 0; c < 64; c++) b = fmaf(sGv2[c], Wn[(64 + c) * 64 + t], b);
    g_gpart[t] = b;
}

// ---------------- final node MLP ----------------
__global__ void k_final(const float* __restrict__ Wn, const float* __restrict__ Wo,
                        const float* __restrict__ bo, float* __restrict__ out) {
    __shared__ float sWn[64 * 64];
    __shared__ float sWo[64], sGp[64];
    for (int i = threadIdx.x; i < 64 * 64; i += blockDim.x) sWn[i] = Wn[i];
    if (threadIdx.x < 64) { sWo[threadIdx.x] = Wo[threadIdx.x]; sGp[threadIdx.x] = g_gpart[threadIdx.x]; }
    __syncthreads();
    int lane = threadIdx.x & 31;
    int warp = (blockIdx.x * blockDim.x + threadIdx.x) >> 5;
    int nwarps = (gridDim.x * blockDim.x) >> 5;
    float b0 = bo[0];
    for (int node = warp; node < GN; node += nwarps) {
        const float* row = g_h2 + (size_t)node * Cc;
        float r0 = row[lane], r1 = row[lane + 32];
        float a0 = 0.f, a1 = 0.f;
#pragma unroll
        for (int c = 0; c < 64; c++) {
            float rc = __shfl_sync(0xffffffffu, c < 32 ? r0 : r1, c & 31);
            a0 = fmaf(rc, sWn[c * 64 + lane], a0);
            a1 = fmaf(rc, sWn[c * 64 + lane + 32], a1);
        }
        float t0 = fmaxf(a0 + sGp[lane], 0.f);
        float t1 = fmaxf(a1 + sGp[lane + 32], 0.f);
        float o = wsum(t0 * sWo[lane] + t1 * sWo[lane + 32]);
        if (lane == 0) out[node] = o + b0;
    }
}

// ---------------- launch ----------------
extern "C" void kernel_launch(void* const* d_in, const int* in_sizes, int n_in,
                              void* d_out, int out_size) {
    const float* x     = (const float*)d_in[0];
    const int*   ei    = (const int*)  d_in[1];
    const float* ew    = (const float*)d_in[2];
    const float* Wl1   = (const float*)d_in[3];
    const float* bl1   = (const float*)d_in[4];
    const float* Wr1   = (const float*)d_in[5];
    const float* br1   = (const float*)d_in[6];
    const float* We1   = (const float*)d_in[7];
    const float* att1  = (const float*)d_in[8];
    const float* bias1 = (const float*)d_in[9];
    const float* Wl2   = (const float*)d_in[10];
    const float* bl2   = (const float*)d_in[11];
    const float* Wr2   = (const float*)d_in[12];
    const float* br2   = (const float*)d_in[13];
    const float* We2   = (const float*)d_in[14];
    const float* att2  = (const float*)d_in[15];
    const float* bias2 = (const float*)d_in[16];
    const float* Wg    = (const float*)d_in[17];
    const float* bg    = (const float*)d_in[18];
    const float* Wn    = (const float*)d_in[19];
    const float* bn    = (const float*)d_in[20];
    const float* Wo    = (const float*)d_in[21];
    const float* bo    = (const float*)d_in[22];
    float* out = (float*)d_out;

    __half *p_xh, *p_w1t, *p_w2t, *p_xl1h, *p_h1h, *p_xl2h;
    float *p_xr1, *p_xr2;
    cudaGetSymbolAddress((void**)&p_xh,   g_xh);
    cudaGetSymbolAddress((void**)&p_w1t,  g_w1t);
    cudaGetSymbolAddress((void**)&p_w2t,  g_w2t);
    cudaGetSymbolAddress((void**)&p_xl1h, g_xl1h);
    cudaGetSymbolAddress((void**)&p_xr1,  g_xr1);
    cudaGetSymbolAddress((void**)&p_h1h,  g_h1h);
    cudaGetSymbolAddress((void**)&p_xl2h, g_xl2h);
    cudaGetSymbolAddress((void**)&p_xr2,  g_xr2);

    const int T = 256;
    k_init<<<(GN + T - 1) / T, T>>>();
    k_cvtx<<<(GN * Ff + T - 1) / T, T>>>(x);
    k_cvtw1<<<(1024 * 128 + T - 1) / T, T>>>(Wl1, Wr1);
    k_cvtw2<<<(128 * 512 + T - 1) / T, T>>>(Wl2, Wr2);
    k_count<<<(GE + T - 1) / T, T>>>(ei, ew);
    k_scan<<<1, 1024>>>();
    k_scatter<<<(GE + T - 1) / T, T>>>(ei, ew);

    // layer-1 GEMMs: logical columns 2*512 = 1024 -> grid.x = 8
    hgemm_dual<<<dim3(8, (GN + 127) / 128), T>>>(p_xh, p_w1t, bl1, br1,
                                                 p_xl1h, p_xr1, GN, HC, Ff);
    k_attn1<<<(GN + 7) / 8, T>>>(We1, att1, bias1);

    // layer-2 GEMMs: logical columns 2*64 = 128 -> grid.x = 1
    hgemm_dual<<<dim3(1, (GN + 127) / 128), T>>>(p_h1h, p_w2t, bl2, br2,
                                                 p_xl2h, p_xr2, GN, Cc, HC);
    k_attn2<<<(GN + 7) / 8, T>>>(We2, att2, bias2);

    k_gmax<<<148, 256>>>();
    k_graphvec<<<1, 64>>>(Wg, bg, Wn, bn);
    k_final<<<1184, 256>>>(Wn, Wo, bo, out);
}

// round 8
// speedup vs baseline: 3.2398x; 1.1158x over previous
#include <cuda_runtime.h>
#include <cuda_fp16.h>
#include <math.h>

#define Gc   2
#define Nn   20000
#define Ee   160000
#define Ff   128
#define Cc   64
#define Hh   8
#define HC   512
#define GN   (Gc * Nn)      // 40000
#define GE   (Gc * Ee)      // 320000

#define MINF_ENC 0x007FFFFFu   // fenc(-inf)

// ---------------- scratch (device globals; no cudaMalloc allowed) ----------
__device__ __half   g_xh  [GN * Ff];    // x in half
__device__ __half   g_w1t [1024 * 128]; // [Wl1|Wr1] transposed [n][k] half
__device__ __half   g_w2t [128 * 512];  // [Wl2|Wr2] transposed [n][k] half
__device__ __half   g_xl1h[GN * HC];    // fp16 xl (layer 1)
__device__ __half   g_xr1h[GN * HC];    // fp16 xr (layer 1)
__device__ __half   g_h1h [GN * HC];    // h1 in half (GEMM2 input)
__device__ __half   g_xl2h[GN * Cc];
__device__ __half   g_xr2h[GN * Cc];
__device__ float    g_h2  [GN * Cc];
__device__ int      g_ideg[GN];
__device__ int      g_off [GN + 1];
__device__ int      g_cur [GN];
__device__ int2     g_edge[GE];         // (src_row, weight bits)
__device__ float    g_loopsum[GN];
__device__ unsigned g_GvEnc[Cc];
__device__ float    g_gpart[Cc];

// ---------------- helpers ----------------
__device__ __forceinline__ unsigned fenc(float f) {
    unsigned u = __float_as_uint(f);
    return (u & 0x80000000u) ? ~u : (u | 0x80000000u);
}
__device__ __forceinline__ float fdec(unsigned u) {
    return __uint_as_float((u & 0x80000000u) ? (u & 0x7fffffffu) : ~u);
}
__device__ __forceinline__ float wsum(float v) {
    v += __shfl_xor_sync(0xffffffffu, v, 16);
    v += __shfl_xor_sync(0xffffffffu, v, 8);
    v += __shfl_xor_sync(0xffffffffu, v, 4);
    v += __shfl_xor_sync(0xffffffffu, v, 2);
    v += __shfl_xor_sync(0xffffffffu, v, 1);
    return v;
}
__device__ __forceinline__ void mma_f16(float* c, const unsigned* a, const unsigned* b) {
    asm volatile(
        "mma.sync.aligned.m16n8k16.row.col.f32.f16.f16.f32 "
        "{%0,%1,%2,%3}, {%4,%5,%6,%7}, {%8,%9}, {%0,%1,%2,%3};"
        : "+f"(c[0]), "+f"(c[1]), "+f"(c[2]), "+f"(c[3])
        : "r"(a[0]), "r"(a[1]), "r"(a[2]), "r"(a[3]), "r"(b[0]), "r"(b[1]));
}
__device__ __forceinline__ void unpack8h(unsigned a, unsigned b, unsigned c, unsigned d, float* o) {
    float2 f;
    f = __half22float2(*(__half2*)&a); o[0] = f.x; o[1] = f.y;
    f = __half22float2(*(__half2*)&b); o[2] = f.x; o[3] = f.y;
    f = __half22float2(*(__half2*)&c); o[4] = f.x; o[5] = f.y;
    f = __half22float2(*(__half2*)&d); o[6] = f.x; o[7] = f.y;
}

// ---------------- merged setup: init + x/W half conversions ----------------
__global__ void k_setup(const float* __restrict__ x,
                        const float* __restrict__ Wl1, const float* __restrict__ Wr1,
                        const float* __restrict__ Wl2, const float* __restrict__ Wr2) {
    int i = blockIdx.x * blockDim.x + threadIdx.x;
    if (i < GN * Ff) g_xh[i] = __float2half(x[i]);
    if (i < 1024 * 128) {
        int n = i >> 7, k = i & 127;
        float v = (n < 512) ? Wl1[k * 512 + n] : Wr1[k * 512 + (n - 512)];
        g_w1t[i] = __float2half(v);
    }
    if (i < 128 * 512) {
        int n = i >> 9, k = i & 511;
        float v = (n < 64) ? Wl2[k * 64 + n] : Wr2[k * 64 + (n - 64)];
        g_w2t[i] = __float2half(v);
    }
    if (i < GN) { g_ideg[i] = 0; g_loopsum[i] = 0.f; }
    if (i < Cc) g_GvEnc[i] = MINF_ENC;
}

// ---------------- degree histogram + loop-weight sum ----------------
__global__ void k_count(const int* __restrict__ ei, const float* __restrict__ ew) {
    int i = blockIdx.x * blockDim.x + threadIdx.x;
    if (i >= GE) return;
    int g = i / Ee, e = i - g * Ee;
    int dst = ei[(size_t)g * 2 * Ee + Ee + e];
    atomicAdd(&g_ideg[g * Nn + dst], 1);
    atomicAdd(&g_loopsum[g * Nn + dst], ew[i]);
}

// ---------------- single-block exclusive scan (warp-shuffle) --------------
__global__ void k_scan() {
    __shared__ int wsums[32];
    int t = threadIdx.x, lane = t & 31, w = t >> 5;
    const int per = (GN + 1023) / 1024;   // 40
    int s = 0;
    for (int i = 0; i < per; i++) {
        int idx = t * per + i;
        if (idx < GN) s += g_ideg[idx];
    }
    // inclusive warp scan of s
    int sc = s;
#pragma unroll
    for (int d = 1; d < 32; d <<= 1) {
        int v = __shfl_up_sync(0xffffffffu, sc, d);
        if (lane >= d) sc += v;
    }
    if (lane == 31) wsums[w] = sc;
    __syncthreads();
    if (w == 0) {
        int v = wsums[lane];
        int vs = v;
#pragma unroll
        for (int d = 1; d < 32; d <<= 1) {
            int u = __shfl_up_sync(0xffffffffu, vs, d);
            if (lane >= d) vs += u;
        }
        wsums[lane] = vs - v;   // exclusive
    }
    __syncthreads();
    int run = wsums[w] + sc - s;   // exclusive prefix for this thread's segment
    for (int i = 0; i < per; i++) {
        int idx = t * per + i;
        if (idx < GN) {
            g_off[idx] = run;
            g_cur[idx] = run;
            run += g_ideg[idx];
        }
    }
    if (t == 0) g_off[GN] = GE;
}

// ---------------- scatter edges into CSR by dst ----------------
__global__ void k_scatter(const int* __restrict__ ei, const float* __restrict__ ew) {
    int i = blockIdx.x * blockDim.x + threadIdx.x;
    if (i >= GE) return;
    int g = i / Ee, e = i - g * Ee;
    int src = ei[(size_t)g * 2 * Ee + e];
    int dst = ei[(size_t)g * 2 * Ee + Ee + e];
    int pos = atomicAdd(&g_cur[g * Nn + dst], 1);
    g_edge[pos] = make_int2(g * Nn + src, __float_as_int(ew[i]));
}

// ---------------- dual-output fp16 tensor-core GEMM (both outputs half) ---
__global__ void hgemm_dual(const __half* __restrict__ A,
                           const __half* __restrict__ Wt,
                           const float* __restrict__ bl, const float* __restrict__ br,
                           __half* __restrict__ Clh, __half* __restrict__ Crh,
                           int M, int N, int K) {
    __shared__ unsigned As2[128][20];
    __shared__ unsigned Bs2[128][20];
    int tid = threadIdx.x;
    int lane = tid & 31;
    int wid = tid >> 5;
    int g = lane >> 2, t = lane & 3;
    int m0w = (wid & 3) * 32;
    int n0w = (wid >> 2) * 64;
    int bm = blockIdx.y * 128, bn = blockIdx.x * 128;

    float acc[2][8][4];
#pragma unroll
    for (int ms = 0; ms < 2; ms++)
#pragma unroll
        for (int ns = 0; ns < 8; ns++)
#pragma unroll
            for (int i = 0; i < 4; i++) acc[ms][ns][i] = 0.f;

    uint4 aST[2], bST[2];

    auto loadG = [&](int k0, uint4* ar, uint4* br_) {
#pragma unroll
        for (int i = 0; i < 2; i++) {
            int qid = tid + i * 256;
            int r = qid >> 2, c = qid & 3;
            uint4 v = make_uint4(0u, 0u, 0u, 0u);
            if (bm + r < M) v = *(const uint4*)(A + (size_t)(bm + r) * K + k0 + c * 8);
            ar[i] = v;
            br_[i] = *(const uint4*)(Wt + (size_t)(bn + r) * K + k0 + c * 8);
        }
    };
    auto stage = [&](const uint4* ar, const uint4* br_) {
#pragma unroll
        for (int i = 0; i < 2; i++) {
            int qid = tid + i * 256;
            int r = qid >> 2, c = qid & 3;
            *(uint4*)&As2[r][c * 4] = ar[i];
            *(uint4*)&Bs2[r][c * 4] = br_[i];
        }
    };

    loadG(0, aST, bST);
    stage(aST, bST);
    __syncthreads();

    for (int k0 = 0; k0 < K; k0 += 32) {
        uint4 aNX[2], bNX[2];
        bool more = (k0 + 32 < K);
        if (more) loadG(k0 + 32, aNX, bNX);

#pragma unroll
        for (int kc = 0; kc < 32; kc += 16) {
            int kw = kc >> 1;
            unsigned af[2][4], bf[8][2];
#pragma unroll
            for (int ms = 0; ms < 2; ms++) {
                int mr = m0w + ms * 16 + g;
                af[ms][0] = As2[mr][kw + t];
                af[ms][1] = As2[mr + 8][kw + t];
                af[ms][2] = As2[mr][kw + t + 4];
                af[ms][3] = As2[mr + 8][kw + t + 4];
            }
#pragma unroll
            for (int ns = 0; ns < 8; ns++) {
                int nc = n0w + ns * 8 + g;
                bf[ns][0] = Bs2[nc][kw + t];
                bf[ns][1] = Bs2[nc][kw + t + 4];
            }
#pragma unroll
            for (int ms = 0; ms < 2; ms++)
#pragma unroll
                for (int ns = 0; ns < 8; ns++)
                    mma_f16(acc[ms][ns], af[ms], bf[ns]);
        }

        if (more) {
            __syncthreads();
            stage(aNX, bNX);
            __syncthreads();
        }
    }

#pragma unroll
    for (int ms = 0; ms < 2; ms++) {
#pragma unroll
        for (int ns = 0; ns < 8; ns++) {
            int cg = bn + n0w + ns * 8 + t * 2;
            int r0 = bm + m0w + ms * 16 + g;
            __half* Cp;
            int cl;
            float b0, b1;
            if (cg < N) { Cp = Clh; cl = cg; b0 = bl[cl]; b1 = bl[cl + 1]; }
            else        { Cp = Crh; cl = cg - N; b0 = br[cl]; b1 = br[cl + 1]; }
            if (r0 < M) {
                __half2 v = __floats2half2_rn(acc[ms][ns][0] + b0, acc[ms][ns][1] + b1);
                *(__half2*)(Cp + (size_t)r0 * N + cl) = v;
            }
            if (r0 + 8 < M) {
                __half2 v = __floats2half2_rn(acc[ms][ns][2] + b0, acc[ms][ns][3] + b1);
                *(__half2*)(Cp + (size_t)(r0 + 8) * N + cl) = v;
            }
        }
    }
}

// ---------------- fused layer-1 attention (prefetch pipeline) -------------
__global__ void k_attn1(const float* __restrict__ We1, const float* __restrict__ att1,
                        const float* __restrict__ bias1) {
    int warp = (blockIdx.x * blockDim.x + threadIdx.x) >> 5;
    int lane = threadIdx.x & 31;
    if (warp >= GN) return;
    int node = warp;
    int base = lane * 16;

    float we[16], at[16], xr[16], acc[16];
    {
        const float4* wep = (const float4*)(We1 + base);
        const float4* atp = (const float4*)(att1 + base);
#pragma unroll
        for (int q = 0; q < 4; q++) {
            float4 a = wep[q]; we[q*4] = a.x; we[q*4+1] = a.y; we[q*4+2] = a.z; we[q*4+3] = a.w;
            float4 b = atp[q]; at[q*4] = b.x; at[q*4+1] = b.y; at[q*4+2] = b.z; at[q*4+3] = b.w;
        }
        const uint4* xrp = (const uint4*)(g_xr1h + (size_t)node * HC + base);
        uint4 u0 = xrp[0], u1 = xrp[1];
        unpack8h(u0.x, u0.y, u0.z, u0.w, xr);
        unpack8h(u1.x, u1.y, u1.z, u1.w, xr + 8);
    }
#pragma unroll
    for (int j = 0; j < 16; j++) acc[j] = 0.f;
    float m = -1e30f, den = 0.f;

    int beg = g_off[node], end = g_off[node + 1];
    float wself = g_loopsum[node] / fmaxf((float)(end - beg), 1.f);

    auto process = [&](uint4 u0, uint4 u1, float w) {
        float xl[16];
        unpack8h(u0.x, u0.y, u0.z, u0.w, xl);
        unpack8h(u1.x, u1.y, u1.z, u1.w, xl + 8);
        float p = 0.f;
#pragma unroll
        for (int j = 0; j < 16; j++) {
            float v = xl[j] + xr[j] + w * we[j];
            v = v > 0.f ? v : 0.2f * v;
            p = fmaf(v, at[j], p);
        }
        p += __shfl_xor_sync(0xffffffffu, p, 1);
        p += __shfl_xor_sync(0xffffffffu, p, 2);
        if (p > m) {
            float sc = __expf(m - p);
            den = den * sc + 1.f;
#pragma unroll
            for (int j = 0; j < 16; j++) acc[j] = fmaf(acc[j], sc, xl[j]);
            m = p;
        } else {
            float c = __expf(p - m);
            den += c;
#pragma unroll
            for (int j = 0; j < 16; j++) acc[j] = fmaf(xl[j], c, acc[j]);
        }
    };

    // prefetch first edge while we fetch the self-loop row
    uint4 n0, n1;
    float nw = 0.f;
    if (beg < end) {
        int2 ed = g_edge[beg];
        nw = __int_as_float(ed.y);
        const uint4* p = (const uint4*)(g_xl1h + (size_t)ed.x * HC + base);
        n0 = p[0]; n1 = p[1];
    }
    {
        const uint4* p = (const uint4*)(g_xl1h + (size_t)node * HC + base);
        uint4 s0 = p[0], s1 = p[1];
        process(s0, s1, wself);
    }
    for (int e = beg; e < end; e++) {
        uint4 c0 = n0, c1 = n1;
        float w = nw;
        if (e + 1 < end) {
            int2 ed = g_edge[e + 1];
            nw = __int_as_float(ed.y);
            const uint4* p = (const uint4*)(g_xl1h + (size_t)ed.x * HC + base);
            n0 = p[0]; n1 = p[1];
        }
        process(c0, c1, w);
    }

    float inv = 1.f / den;
    __half* o = g_h1h + (size_t)node * HC + base;
    const float* bi = bias1 + base;
#pragma unroll
    for (int q = 0; q < 8; q++) {
        float v0 = acc[2*q]     * inv + bi[2*q];
        float v1 = acc[2*q + 1] * inv + bi[2*q + 1];
        v0 = v0 > 0.f ? v0 : (__expf(v0) - 1.f);
        v1 = v1 > 0.f ? v1 : (__expf(v1) - 1.f);
        *(__half2*)(o + 2*q) = __floats2half2_rn(v0, v1);
    }
}

// ---------------- fused layer-2 attention (prefetch pipeline) -------------
__global__ void k_attn2(const float* __restrict__ We2, const float* __restrict__ att2,
                        const float* __restrict__ bias2) {
    int warp = (blockIdx.x * blockDim.x + threadIdx.x) >> 5;
    int lane = threadIdx.x & 31;
    if (warp >= GN) return;
    int node = warp;
    int b2 = lane * 2;

    float2 we = *(const float2*)(We2 + b2);
    float2 at = *(const float2*)(att2 + b2);
    float2 xr = __half22float2(*(const __half2*)(g_xr2h + (size_t)node * Cc + b2));
    float acc0 = 0.f, acc1 = 0.f, m = -1e30f, den = 0.f;

    int beg = g_off[node], end = g_off[node + 1];
    float wself = g_loopsum[node] / fmaxf((float)(end - beg), 1.f);

    auto process = [&](unsigned u, float w) {
        float2 xl = __half22float2(*(__half2*)&u);
        float v0 = xl.x + xr.x + w * we.x;
        float v1 = xl.y + xr.y + w * we.y;
        v0 = v0 > 0.f ? v0 : 0.2f * v0;
        v1 = v1 > 0.f ? v1 : 0.2f * v1;
        float p = wsum(fmaf(v0, at.x, v1 * at.y));
        if (p > m) {
            float sc = __expf(m - p);
            den = den * sc + 1.f;
            acc0 = fmaf(acc0, sc, xl.x);
            acc1 = fmaf(acc1, sc, xl.y);
            m = p;
        } else {
            float c = __expf(p - m);
            den += c;
            acc0 = fmaf(xl.x, c, acc0);
            acc1 = fmaf(xl.y, c, acc1);
        }
    };

    unsigned nx = 0u;
    float nw = 0.f;
    if (beg < end) {
        int2 ed = g_edge[beg];
        nw = __int_as_float(ed.y);
        nx = *(const unsigned*)(g_xl2h + (size_t)ed.x * Cc + b2);
    }
    {
        unsigned su = *(const unsigned*)(g_xl2h + (size_t)node * Cc + b2);
        process(su, wself);
    }
    for (int e = beg; e < end; e++) {
        unsigned cu = nx;
        float w = nw;
        if (e + 1 < end) {
            int2 ed = g_edge[e + 1];
            nw = __int_as_float(ed.y);
            nx = *(const unsigned*)(g_xl2h + (size_t)ed.x * Cc + b2);
        }
        process(cu, w);
    }

    float inv = 1.f / den;
    float v0 = acc0 * inv + bias2[b2];
    float v1 = acc1 * inv + bias2[b2 + 1];
    v0 = v0 > 0.f ? v0 : (__expf(v0) - 1.f);
    v1 = v1 > 0.f ? v1 : (__expf(v1) - 1.f);
    float* o = g_h2 + (size_t)node * Cc + b2;
    o[0] = v0; o[1] = v1;
}

// ---------------- global max over all nodes/graphs ----------------
__global__ void k_gmax() {
    int col = threadIdx.x & 63;
    int rg = threadIdx.x >> 6;
    float m = -1e30f;
    for (int row = blockIdx.x * 4 + rg; row < GN; row += gridDim.x * 4)
        m = fmaxf(m, g_h2[(size_t)row * Cc + col]);
    __shared__ float sm[256];
    sm[threadIdx.x] = m;
    __syncthreads();
    if (threadIdx.x < 64) {
        float v = fmaxf(fmaxf(sm[threadIdx.x], sm[threadIdx.x + 64]),
                        fmaxf(sm[threadIdx.x + 128], sm[threadIdx.x + 192]));
        atomicMax(&g_GvEnc[threadIdx.x], fenc(v));
    }
}

// ---------------- graph vector path ----------------
__global__ void k_graphvec(const float* __restrict__ Wg, const float* __restrict__ bg,
                           const float* __restrict__ Wn, const float* __restrict__ bn) {
    __shared__ float sGv[64], sGv2[64];
    int t = threadIdx.x;
    sGv[t] = fdec(g_GvEnc[t]);
    __syncthreads();
    float a = bg[t];
#pragma unroll
    for (int c = 0; c < 64; c++) a = fmaf(sGv[c], Wg[c * 64 + t], a);
    sGv2[t] = fmaxf(a, 0.f);
    __syncthreads();
    float b = bn[t];
#pragma unroll
    for (int c = 0; c < 64; c++) b = fmaf(sGv2[c], Wn[(64 + c) * 64 + t], b);
    g_gpart[t] = b;
}

// ---------------- final node MLP ----------------
__global__ void k_final(const float* __restrict__ Wn, const float* __restrict__ Wo,
                        const float* __restrict__ bo, float* __restrict__ out) {
    __shared__ float sWn[64 * 64];
    __shared__ float sWo[64], sGp[64];
    for (int i = threadIdx.x; i < 64 * 64; i += blockDim.x) sWn[i] = Wn[i];
    if (threadIdx.x < 64) { sWo[threadIdx.x] = Wo[threadIdx.x]; sGp[threadIdx.x] = g_gpart[threadIdx.x]; }
    __syncthreads();
    int lane = threadIdx.x & 31;
    int warp = (blockIdx.x * blockDim.x + threadIdx.x) >> 5;
    int nwarps = (gridDim.x * blockDim.x) >> 5;
    float b0 = bo[0];
    for (int node = warp; node < GN; node += nwarps) {
        const float* row = g_h2 + (size_t)node * Cc;
        float r0 = row[lane], r1 = row[lane + 32];
        float a0 = 0.f, a1 = 0.f;
#pragma unroll
        for (int c = 0; c < 64; c++) {
            float rc = __shfl_sync(0xffffffffu, c < 32 ? r0 : r1, c & 31);
            a0 = fmaf(rc, sWn[c * 64 + lane], a0);
            a1 = fmaf(rc, sWn[c * 64 + lane + 32], a1);
        }
        float t0 = fmaxf(a0 + sGp[lane], 0.f);
        float t1 = fmaxf(a1 + sGp[lane + 32], 0.f);
        float o = wsum(t0 * sWo[lane] + t1 * sWo[lane + 32]);
        if (lane == 0) out[node] = o + b0;
    }
}

// ---------------- launch ----------------
extern "C" void kernel_launch(void* const* d_in, const int* in_sizes, int n_in,
                              void* d_out, int out_size) {
    const float* x     = (const float*)d_in[0];
    const int*   ei    = (const int*)  d_in[1];
    const float* ew    = (const float*)d_in[2];
    const float* Wl1   = (const float*)d_in[3];
    const float* bl1   = (const float*)d_in[4];
    const float* Wr1   = (const float*)d_in[5];
    const float* br1   = (const float*)d_in[6];
    const float* We1   = (const float*)d_in[7];
    const float* att1  = (const float*)d_in[8];
    const float* bias1 = (const float*)d_in[9];
    const float* Wl2   = (const float*)d_in[10];
    const float* bl2   = (const float*)d_in[11];
    const float* Wr2   = (const float*)d_in[12];
    const float* br2   = (const float*)d_in[13];
    const float* We2   = (const float*)d_in[14];
    const float* att2  = (const float*)d_in[15];
    const float* bias2 = (const float*)d_in[16];
    const float* Wg    = (const float*)d_in[17];
    const float* bg    = (const float*)d_in[18];
    const float* Wn    = (const float*)d_in[19];
    const float* bn    = (const float*)d_in[20];
    const float* Wo    = (const float*)d_in[21];
    const float* bo    = (const float*)d_in[22];
    float* out = (float*)d_out;

    __half *p_xh, *p_w1t, *p_w2t, *p_xl1h, *p_xr1h, *p_h1h, *p_xl2h, *p_xr2h;
    cudaGetSymbolAddress((void**)&p_xh,   g_xh);
    cudaGetSymbolAddress((void**)&p_w1t,  g_w1t);
    cudaGetSymbolAddress((void**)&p_w2t,  g_w2t);
    cudaGetSymbolAddress((void**)&p_xl1h, g_xl1h);
    cudaGetSymbolAddress((void**)&p_xr1h, g_xr1h);
    cudaGetSymbolAddress((void**)&p_h1h,  g_h1h);
    cudaGetSymbolAddress((void**)&p_xl2h, g_xl2h);
    cudaGetSymbolAddress((void**)&p_xr2h, g_xr2h);

    const int T = 256;
    k_setup<<<(GN * Ff + T - 1) / T, T>>>(x, Wl1, Wr1, Wl2, Wr2);
    k_count<<<(GE + T - 1) / T, T>>>(ei, ew);
    k_scan<<<1, 1024>>>();
    k_scatter<<<(GE + T - 1) / T, T>>>(ei, ew);

    // layer-1 GEMMs: logical columns 2*512 = 1024 -> grid.x = 8
    hgemm_dual<<<dim3(8, (GN + 127) / 128), T>>>(p_xh, p_w1t, bl1, br1,
                                                 p_xl1h, p_xr1h, GN, HC, Ff);
    k_attn1<<<(GN + 7) / 8, T>>>(We1, att1, bias1);

    // layer-2 GEMMs: logical columns 2*64 = 128 -> grid.x = 1
    hgemm_dual<<<dim3(1, (GN + 127) / 128), T>>>(p_h1h, p_w2t, bl2, br2,
                                                 p_xl2h, p_xr2h, GN, Cc, HC);
    k_attn2<<<(GN + 7) / 8, T>>>(We2, att2, bias2);

    k_gmax<<<148, 256>>>();
    k_graphvec<<<1, 64>>>(Wg, bg, Wn, bn);
    k_final<<<1184, 256>>>(Wn, Wo, bo, out);
}

// round 10
// speedup vs baseline: 3.4479x; 1.0642x over previous
#include <cuda_runtime.h>
#include <cuda_fp16.h>
#include <math.h>

#define Gc   2
#define Nn   20000
#define Ee   160000
#define Ff   128
#define Cc   64
#define Hh   8
#define HC   512
#define GN   (Gc * Nn)      // 40000
#define GE   (Gc * Ee)      // 320000

#define MINF_ENC 0x007FFFFFu   // fenc(-inf)

// ---------------- scratch (device globals; no cudaMalloc allowed) ----------
__device__ __half   g_xh  [GN * Ff];    // x in half
__device__ __half   g_w1t [1024 * 128]; // [Wl1|Wr1] transposed [n][k] half
__device__ __half   g_w2t [128 * 512];  // [Wl2|Wr2] transposed [n][k] half
__device__ __half   g_xl1h[GN * HC];    // fp16 xl (layer 1)
__device__ __half   g_xr1h[GN * HC];    // fp16 xr (layer 1)
__device__ __half   g_h1h [GN * HC];    // h1 in half (GEMM2 input)
__device__ __half   g_xl2h[GN * Cc];
__device__ __half   g_xr2h[GN * Cc];
__device__ float    g_h2  [GN * Cc];
__device__ int      g_ideg[GN];
__device__ int      g_off [GN + 1];
__device__ int      g_cur [GN];
__device__ int2     g_edge[GE];         // (src_row, weight bits)
__device__ float    g_loopsum[GN];
__device__ unsigned g_GvEnc[Cc];
__device__ float    g_gpart[Cc];

// ---------------- helpers ----------------
__device__ __forceinline__ unsigned fenc(float f) {
    unsigned u = __float_as_uint(f);
    return (u & 0x80000000u) ? ~u : (u | 0x80000000u);
}
__device__ __forceinline__ float fdec(unsigned u) {
    return __uint_as_float((u & 0x80000000u) ? (u & 0x7fffffffu) : ~u);
}
__device__ __forceinline__ float wsum(float v) {
    v += __shfl_xor_sync(0xffffffffu, v, 16);
    v += __shfl_xor_sync(0xffffffffu, v, 8);
    v += __shfl_xor_sync(0xffffffffu, v, 4);
    v += __shfl_xor_sync(0xffffffffu, v, 2);
    v += __shfl_xor_sync(0xffffffffu, v, 1);
    return v;
}
__device__ __forceinline__ void mma_f16(float* c, const unsigned* a, const unsigned* b) {
    asm volatile(
        "mma.sync.aligned.m16n8k16.row.col.f32.f16.f16.f32 "
        "{%0,%1,%2,%3}, {%4,%5,%6,%7}, {%8,%9}, {%0,%1,%2,%3};"
        : "+f"(c[0]), "+f"(c[1]), "+f"(c[2]), "+f"(c[3])
        : "r"(a[0]), "r"(a[1]), "r"(a[2]), "r"(a[3]), "r"(b[0]), "r"(b[1]));
}
__device__ __forceinline__ void unpack4h(unsigned a, unsigned b, unsigned c, unsigned d, float* o) {
    float2 f;
    f = __half22float2(*(__half2*)&a); o[0] = f.x; o[1] = f.y;
    f = __half22float2(*(__half2*)&b); o[2] = f.x; o[3] = f.y;
    f = __half22float2(*(__half2*)&c); o[4] = f.x; o[5] = f.y;
    f = __half22float2(*(__half2*)&d); o[6] = f.x; o[7] = f.y;
}

// ---------------- merged setup: init + x/W half conversions ----------------
__global__ void k_setup(const float* __restrict__ x,
                        const float* __restrict__ Wl1, const float* __restrict__ Wr1,
                        const float* __restrict__ Wl2, const float* __restrict__ Wr2) {
    int i = blockIdx.x * blockDim.x + threadIdx.x;
    if (i < GN * Ff) g_xh[i] = __float2half(x[i]);
    if (i < 1024 * 128) {
        int n = i >> 7, k = i & 127;
        float v = (n < 512) ? Wl1[k * 512 + n] : Wr1[k * 512 + (n - 512)];
        g_w1t[i] = __float2half(v);
    }
    if (i < 128 * 512) {
        int n = i >> 9, k = i & 511;
        float v = (n < 64) ? Wl2[k * 64 + n] : Wr2[k * 64 + (n - 64)];
        g_w2t[i] = __float2half(v);
    }
    if (i < GN) { g_ideg[i] = 0; g_loopsum[i] = 0.f; }
    if (i < Cc) g_GvEnc[i] = MINF_ENC;
}

// ---------------- degree histogram + loop-weight sum ----------------
__global__ void k_count(const int* __restrict__ ei, const float* __restrict__ ew) {
    int i = blockIdx.x * blockDim.x + threadIdx.x;
    if (i >= GE) return;
    int g = i / Ee, e = i - g * Ee;
    int dst = ei[(size_t)g * 2 * Ee + Ee + e];
    atomicAdd(&g_ideg[g * Nn + dst], 1);
    atomicAdd(&g_loopsum[g * Nn + dst], ew[i]);
}

// ---------------- single-block exclusive scan (warp-shuffle) --------------
__global__ void k_scan() {
    __shared__ int wsums[32];
    int t = threadIdx.x, lane = t & 31, w = t >> 5;
    const int per = (GN + 1023) / 1024;   // 40
    int s = 0;
    for (int i = 0; i < per; i++) {
        int idx = t * per + i;
        if (idx < GN) s += g_ideg[idx];
    }
    int sc = s;
#pragma unroll
    for (int d = 1; d < 32; d <<= 1) {
        int v = __shfl_up_sync(0xffffffffu, sc, d);
        if (lane >= d) sc += v;
    }
    if (lane == 31) wsums[w] = sc;
    __syncthreads();
    if (w == 0) {
        int v = wsums[lane];
        int vs = v;
#pragma unroll
        for (int d = 1; d < 32; d <<= 1) {
            int u = __shfl_up_sync(0xffffffffu, vs, d);
            if (lane >= d) vs += u;
        }
        wsums[lane] = vs - v;
    }
    __syncthreads();
    int run = wsums[w] + sc - s;
    for (int i = 0; i < per; i++) {
        int idx = t * per + i;
        if (idx < GN) {
            g_off[idx] = run;
            g_cur[idx] = run;
            run += g_ideg[idx];
        }
    }
    if (t == 0) g_off[GN] = GE;
}

// ---------------- scatter edges into CSR by dst ----------------
__global__ void k_scatter(const int* __restrict__ ei, const float* __restrict__ ew) {
    int i = blockIdx.x * blockDim.x + threadIdx.x;
    if (i >= GE) return;
    int g = i / Ee, e = i - g * Ee;
    int src = ei[(size_t)g * 2 * Ee + e];
    int dst = ei[(size_t)g * 2 * Ee + Ee + e];
    int pos = atomicAdd(&g_cur[g * Nn + dst], 1);
    g_edge[pos] = make_int2(g * Nn + src, __float_as_int(ew[i]));
}

// ---------------- dual-output fp16 tensor-core GEMM (both outputs half) ---
__global__ void hgemm_dual(const __half* __restrict__ A,
                           const __half* __restrict__ Wt,
                           const float* __restrict__ bl, const float* __restrict__ br,
                           __half* __restrict__ Clh, __half* __restrict__ Crh,
                           int M, int N, int K) {
    __shared__ unsigned As2[128][20];
    __shared__ unsigned Bs2[128][20];
    int tid = threadIdx.x;
    int lane = tid & 31;
    int wid = tid >> 5;
    int g = lane >> 2, t = lane & 3;
    int m0w = (wid & 3) * 32;
    int n0w = (wid >> 2) * 64;
    int bm = blockIdx.y * 128, bn = blockIdx.x * 128;

    float acc[2][8][4];
#pragma unroll
    for (int ms = 0; ms < 2; ms++)
#pragma unroll
        for (int ns = 0; ns < 8; ns++)
#pragma unroll
            for (int i = 0; i < 4; i++) acc[ms][ns][i] = 0.f;

    uint4 aST[2], bST[2];

    auto loadG = [&](int k0, uint4* ar, uint4* br_) {
#pragma unroll
        for (int i = 0; i < 2; i++) {
            int qid = tid + i * 256;
            int r = qid >> 2, c = qid & 3;
            uint4 v = make_uint4(0u, 0u, 0u, 0u);
            if (bm + r < M) v = *(const uint4*)(A + (size_t)(bm + r) * K + k0 + c * 8);
            ar[i] = v;
            br_[i] = *(const uint4*)(Wt + (size_t)(bn + r) * K + k0 + c * 8);
        }
    };
    auto stage = [&](const uint4* ar, const uint4* br_) {
#pragma unroll
        for (int i = 0; i < 2; i++) {
            int qid = tid + i * 256;
            int r = qid >> 2, c = qid & 3;
            *(uint4*)&As2[r][c * 4] = ar[i];
            *(uint4*)&Bs2[r][c * 4] = br_[i];
        }
    };

    loadG(0, aST, bST);
    stage(aST, bST);
    __syncthreads();

    for (int k0 = 0; k0 < K; k0 += 32) {
        uint4 aNX[2], bNX[2];
        bool more = (k0 + 32 < K);
        if (more) loadG(k0 + 32, aNX, bNX);

#pragma unroll
        for (int kc = 0; kc < 32; kc += 16) {
            int kw = kc >> 1;
            unsigned af[2][4], bf[8][2];
#pragma unroll
            for (int ms = 0; ms < 2; ms++) {
                int mr = m0w + ms * 16 + g;
                af[ms][0] = As2[mr][kw + t];
                af[ms][1] = As2[mr + 8][kw + t];
                af[ms][2] = As2[mr][kw + t + 4];
                af[ms][3] = As2[mr + 8][kw + t + 4];
            }
#pragma unroll
            for (int ns = 0; ns < 8; ns++) {
                int nc = n0w + ns * 8 + g;
                bf[ns][0] = Bs2[nc][kw + t];
                bf[ns][1] = Bs2[nc][kw + t + 4];
            }
#pragma unroll
            for (int ms = 0; ms < 2; ms++)
#pragma unroll
                for (int ns = 0; ns < 8; ns++)
                    mma_f16(acc[ms][ns], af[ms], bf[ns]);
        }

        if (more) {
            __syncthreads();
            stage(aNX, bNX);
            __syncthreads();
        }
    }

#pragma unroll
    for (int ms = 0; ms < 2; ms++) {
#pragma unroll
        for (int ns = 0; ns < 8; ns++) {
            int cg = bn + n0w + ns * 8 + t * 2;
            int r0 = bm + m0w + ms * 16 + g;
            __half* Cp;
            int cl;
            float b0, b1;
            if (cg < N) { Cp = Clh; cl = cg; b0 = bl[cl]; b1 = bl[cl + 1]; }
            else        { Cp = Crh; cl = cg - N; b0 = br[cl]; b1 = br[cl + 1]; }
            if (r0 < M) {
                __half2 v = __floats2half2_rn(acc[ms][ns][0] + b0, acc[ms][ns][1] + b1);
                *(__half2*)(Cp + (size_t)r0 * N + cl) = v;
            }
            if (r0 + 8 < M) {
                __half2 v = __floats2half2_rn(acc[ms][ns][2] + b0, acc[ms][ns][3] + b1);
                *(__half2*)(Cp + (size_t)(r0 + 8) * N + cl) = v;
            }
        }
    }
}

// ---------------- fused layer-1 attention: 2 warps per node ----------------
// warp = node*2 + half; warp owns 4 heads (256 cols); lane owns 8 cols.
// head = 8-lane group; logit reduce via shfl_xor 1,2,4.
__global__ void k_attn1(const float* __restrict__ We1, const float* __restrict__ att1,
                        const float* __restrict__ bias1) {
    int gw = (blockIdx.x * blockDim.x + threadIdx.x) >> 5;
    int lane = threadIdx.x & 31;
    if (gw >= GN * 2) return;
    int node = gw >> 1;
    int half = gw & 1;
    int base = half * 256 + lane * 8;

    float we[8], at[8], xr[8], acc[8];
    {
        const float4* wep = (const float4*)(We1 + base);
        const float4* atp = (const float4*)(att1 + base);
#pragma unroll
        for (int q = 0; q < 2; q++) {
            float4 a = wep[q]; we[q*4] = a.x; we[q*4+1] = a.y; we[q*4+2] = a.z; we[q*4+3] = a.w;
            float4 b = atp[q]; at[q*4] = b.x; at[q*4+1] = b.y; at[q*4+2] = b.z; at[q*4+3] = b.w;
        }
        uint4 u = *(const uint4*)(g_xr1h + (size_t)node * HC + base);
        unpack4h(u.x, u.y, u.z, u.w, xr);
    }
#pragma unroll
    for (int j = 0; j < 8; j++) acc[j] = 0.f;
    float m = -1e30f, den = 0.f;

    int beg = g_off[node], end = g_off[node + 1];
    float wself = g_loopsum[node] / fmaxf((float)(end - beg), 1.f);

    auto process = [&](uint4 u, float w) {
        float xl[8];
        unpack4h(u.x, u.y, u.z, u.w, xl);
        float p = 0.f;
#pragma unroll
        for (int j = 0; j < 8; j++) {
            float v = xl[j] + xr[j] + w * we[j];
            v = v > 0.f ? v : 0.2f * v;
            p = fmaf(v, at[j], p);
        }
        // reduce within 8-lane head group
        p += __shfl_xor_sync(0xffffffffu, p, 1);
        p += __shfl_xor_sync(0xffffffffu, p, 2);
        p += __shfl_xor_sync(0xffffffffu, p, 4);
        if (p > m) {
            float sc = __expf(m - p);
            den = den * sc + 1.f;
#pragma unroll
            for (int j = 0; j < 8; j++) acc[j] = fmaf(acc[j], sc, xl[j]);
            m = p;
        } else {
            float c = __expf(p - m);
            den += c;
#pragma unroll
            for (int j = 0; j < 8; j++) acc[j] = fmaf(xl[j], c, acc[j]);
        }
    };

    uint4 nx;
    float nw = 0.f;
    if (beg < end) {
        int2 ed = g_edge[beg];
        nw = __int_as_float(ed.y);
        nx = *(const uint4*)(g_xl1h + (size_t)ed.x * HC + base);
    }
    {
        uint4 su = *(const uint4*)(g_xl1h + (size_t)node * HC + base);
        process(su, wself);
    }
    for (int e = beg; e < end; e++) {
        uint4 cu = nx;
        float w = nw;
        if (e + 1 < end) {
            int2 ed = g_edge[e + 1];
            nw = __int_as_float(ed.y);
            nx = *(const uint4*)(g_xl1h + (size_t)ed.x * HC + base);
        }
        process(cu, w);
    }

    float inv = 1.f / den;
    __half* o = g_h1h + (size_t)node * HC + base;
    const float* bi = bias1 + base;
#pragma unroll
    for (int q = 0; q < 4; q++) {
        float v0 = acc[2*q]     * inv + bi[2*q];
        float v1 = acc[2*q + 1] * inv + bi[2*q + 1];
        v0 = v0 > 0.f ? v0 : (__expf(v0) - 1.f);
        v1 = v1 > 0.f ? v1 : (__expf(v1) - 1.f);
        *(__half2*)(o + 2*q) = __floats2half2_rn(v0, v1);
    }
}

// ---------------- fused layer-2 attention (prefetch pipeline) -------------
__global__ void k_attn2(const float* __restrict__ We2, const float* __restrict__ att2,
                        const float* __restrict__ bias2) {
    int warp = (blockIdx.x * blockDim.x + threadIdx.x) >> 5;
    int lane = threadIdx.x & 31;
    if (warp >= GN) return;
    int node = warp;
    int b2 = lane * 2;

    float2 we = *(const float2*)(We2 + b2);
    float2 at = *(const float2*)(att2 + b2);
    float2 xr = __half22float2(*(const __half2*)(g_xr2h + (size_t)node * Cc + b2));
    float acc0 = 0.f, acc1 = 0.f, m = -1e30f, den = 0.f;

    int beg = g_off[node], end = g_off[node + 1];
    float wself = g_loopsum[node] / fmaxf((float)(end - beg), 1.f);

    auto process = [&](unsigned u, float w) {
        float2 xl = __half22float2(*(__half2*)&u);
        float v0 = xl.x + xr.x + w * we.x;
        float v1 = xl.y + xr.y + w * we.y;
        v0 = v0 > 0.f ? v0 : 0.2f * v0;
        v1 = v1 > 0.f ? v1 : 0.2f * v1;
        float p = wsum(fmaf(v0, at.x, v1 * at.y));
        if (p > m) {
            float sc = __expf(m - p);
            den = den * sc + 1.f;
            acc0 = fmaf(acc0, sc, xl.x);
            acc1 = fmaf(acc1, sc, xl.y);
            m = p;
        } else {
            float c = __expf(p - m);
            den += c;
            acc0 = fmaf(xl.x, c, acc0);
            acc1 = fmaf(xl.y, c, acc1);
        }
    };

    unsigned nx = 0u;
    float nw = 0.f;
    if (beg < end) {
        int2 ed = g_edge[beg];
        nw = __int_as_float(ed.y);
        nx = *(const unsigned*)(g_xl2h + (size_t)ed.x * Cc + b2);
    }
    {
        unsigned su = *(const unsigned*)(g_xl2h + (size_t)node * Cc + b2);
        process(su, wself);
    }
    for (int e = beg; e < end; e++) {
        unsigned cu = nx;
        float w = nw;
        if (e + 1 < end) {
            int2 ed = g_edge[e + 1];
            nw = __int_as_float(ed.y);
            nx = *(const unsigned*)(g_xl2h + (size_t)ed.x * Cc + b2);
        }
        process(cu, w);
    }

    float inv = 1.f / den;
    float v0 = acc0 * inv + bias2[b2];
    float v1 = acc1 * inv + bias2[b2 + 1];
    v0 = v0 > 0.f ? v0 : (__expf(v0) - 1.f);
    v1 = v1 > 0.f ? v1 : (__expf(v1) - 1.f);
    float* o = g_h2 + (size_t)node * Cc + b2;
    o[0] = v0; o[1] = v1;
}

// ---------------- global max over all nodes/graphs ----------------
__global__ void k_gmax() {
    int col = threadIdx.x & 63;
    int rg = threadIdx.x >> 6;
    float m = -1e30f;
    for (int row = blockIdx.x * 4 + rg; row < GN; row += gridDim.x * 4)
        m = fmaxf(m, g_h2[(size_t)row * Cc + col]);
    __shared__ float sm[256];
    sm[threadIdx.x] = m;
    __syncthreads();
    if (threadIdx.x < 64) {
        float v = fmaxf(fmaxf(sm[threadIdx.x], sm[threadIdx.x + 64]),
                        fmaxf(sm[threadIdx.x + 128], sm[threadIdx.x + 192]));
        atomicMax(&g_GvEnc[threadIdx.x], fenc(v));
    }
}

// ---------------- graph vector path ----------------
__global__ void k_graphvec(const float* __restrict__ Wg, const float* __restrict__ bg,
                           const float* __restrict__ Wn, const float* __restrict__ bn) {
    __shared__ float sGv[64], sGv2[64];
    int t = threadIdx.x;
    sGv[t] = fdec(g_GvEnc[t]);
    __syncthreads();
    float a = bg[t];
#pragma unroll
    for (int c = 0; c < 64; c++) a = fmaf(sGv[c], Wg[c * 64 + t], a);
    sGv2[t] = fmaxf(a, 0.f);
    __syncthreads();
    float b = bn[t];
#pragma unroll
    for (int c = 0; c < 64; c++) b = fmaf(sGv2[c], Wn[(64 + c) * 64 + t], b);
    g_gpart[t] = b;
}

// ---------------- final node MLP ----------------
__global__ void k_final(const float* __restrict__ Wn, const float* __restrict__ Wo,
                        const float* __restrict__ bo, float* __restrict__ out) {
    __shared__ float sWn[64 * 64];
    __shared__ float sWo[64], sGp[64];
    for (int i = threadIdx.x; i < 64 * 64; i += blockDim.x) sWn[i] = Wn[i];
    if (threadIdx.x < 64) { sWo[threadIdx.x] = Wo[threadIdx.x]; sGp[threadIdx.x] = g_gpart[threadIdx.x]; }
    __syncthreads();
    int lane = threadIdx.x & 31;
    int warp = (blockIdx.x * blockDim.x + threadIdx.x) >> 5;
    int nwarps = (gridDim.x * blockDim.x) >> 5;
    float b0 = bo[0];
    for (int node = warp; node < GN; node += nwarps) {
        const float* row = g_h2 + (size_t)node * Cc;
        float r0 = row[lane], r1 = row[lane + 32];
        float a0 = 0.f, a1 = 0.f;
#pragma unroll
        for (int c = 0; c < 64; c++) {
            float rc = __shfl_sync(0xffffffffu, c < 32 ? r0 : r1, c & 31);
            a0 = fmaf(rc, sWn[c * 64 + lane], a0);
            a1 = fmaf(rc, sWn[c * 64 + lane + 32], a1);
        }
        float t0 = fmaxf(a0 + sGp[lane], 0.f);
        float t1 = fmaxf(a1 + sGp[lane + 32], 0.f);
        float o = wsum(t0 * sWo[lane] + t1 * sWo[lane + 32]);
        if (lane == 0) out[node] = o + b0;
    }
}

// ---------------- launch ----------------
extern "C" void kernel_launch(void* const* d_in, const int* in_sizes, int n_in,
                              void* d_out, int out_size) {
    const float* x     = (const float*)d_in[0];
    const int*   ei    = (const int*)  d_in[1];
    const float* ew    = (const float*)d_in[2];
    const float* Wl1   = (const float*)d_in[3];
    const float* bl1   = (const float*)d_in[4];
    const float* Wr1   = (const float*)d_in[5];
    const float* br1   = (const float*)d_in[6];
    const float* We1   = (const float*)d_in[7];
    const float* att1  = (const float*)d_in[8];
    const float* bias1 = (const float*)d_in[9];
    const float* Wl2   = (const float*)d_in[10];
    const float* bl2   = (const float*)d_in[11];
    const float* Wr2   = (const float*)d_in[12];
    const float* br2   = (const float*)d_in[13];
    const float* We2   = (const float*)d_in[14];
    const float* att2  = (const float*)d_in[15];
    const float* bias2 = (const float*)d_in[16];
    const float* Wg    = (const float*)d_in[17];
    const float* bg    = (const float*)d_in[18];
    const float* Wn    = (const float*)d_in[19];
    const float* bn    = (const float*)d_in[20];
    const float* Wo    = (const float*)d_in[21];
    const float* bo    = (const float*)d_in[22];
    float* out = (float*)d_out;

    __half *p_xh, *p_w1t, *p_w2t, *p_xl1h, *p_xr1h, *p_h1h, *p_xl2h, *p_xr2h;
    cudaGetSymbolAddress((void**)&p_xh,   g_xh);
    cudaGetSymbolAddress((void**)&p_w1t,  g_w1t);
    cudaGetSymbolAddress((void**)&p_w2t,  g_w2t);
    cudaGetSymbolAddress((void**)&p_xl1h, g_xl1h);
    cudaGetSymbolAddress((void**)&p_xr1h, g_xr1h);
    cudaGetSymbolAddress((void**)&p_h1h,  g_h1h);
    cudaGetSymbolAddress((void**)&p_xl2h, g_xl2h);
    cudaGetSymbolAddress((void**)&p_xr2h, g_xr2h);

    const int T = 256;
    k_setup<<<(GN * Ff + T - 1) / T, T>>>(x, Wl1, Wr1, Wl2, Wr2);
    k_count<<<(GE + T - 1) / T, T>>>(ei, ew);
    k_scan<<<1, 1024>>>();
    k_scatter<<<(GE + T - 1) / T, T>>>(ei, ew);

    // layer-1 GEMMs: logical columns 2*512 = 1024 -> grid.x = 8
    hgemm_dual<<<dim3(8, (GN + 127) / 128), T>>>(p_xh, p_w1t, bl1, br1,
                                                 p_xl1h, p_xr1h, GN, HC, Ff);
    // 2 warps per node -> GN*2 warps
    k_attn1<<<(GN * 2 + 7) / 8, T>>>(We1, att1, bias1);

    // layer-2 GEMMs: logical columns 2*64 = 128 -> grid.x = 1
    hgemm_dual<<<dim3(1, (GN + 127) / 128), T>>>(p_h1h, p_w2t, bl2, br2,
                                                 p_xl2h, p_xr2h, GN, Cc, HC);
    k_attn2<<<(GN + 7) / 8, T>>>(We2, att2, bias2);

    k_gmax<<<148, 256>>>();
    k_graphvec<<<1, 64>>>(Wg, bg, Wn, bn);
    k_final<<<1184, 256>>>(Wn, Wo, bo, out);
}